// round 7
// baseline (speedup 1.0000x reference)
#include <cuda_runtime.h>
#include <cstdint>

#define BATCH 2
#define DIM   128
#define HS    62
#define HX    248
#define PS_S  (HS*HS)   // 3844
#define PS_X  (HX*HX)   // 61504
#define NWIN  100       // 10x10 windows

// ---------------- scratch ----------------------------------------------------
__device__ float g_xp  [BATCH*DIM*PS_X];
__device__ float g_spp [BATCH*DIM*PS_S];
__device__ float g_tkv [BATCH*2*DIM*PS_X];
__device__ float g_kv  [BATCH*2*DIM*PS_X];   // tf32-rounded values
__device__ float g_tq  [BATCH*DIM*PS_S];
__device__ float g_q   [BATCH*DIM*PS_S];     // tf32-rounded, scale folded
__device__ float g_win [BATCH*NWIN*DIM*64];
__device__ float g_wq_t  [DIM*DIM];
__device__ float g_wkv_t [DIM*2*DIM];
__device__ float g_wout_t[DIM*DIM];

__device__ __forceinline__ uint32_t f2tf32(float f) {
    uint32_t u;
    asm("cvt.rna.tf32.f32 %0, %1;" : "=r"(u) : "f"(f));
    return u;
}

#define MMA_TF32(C0,C1,C2,C3,A0,A1,A2,A3,B0,B1)                               \
    asm volatile(                                                             \
        "mma.sync.aligned.m16n8k8.row.col.f32.tf32.tf32.f32 "                 \
        "{%0,%1,%2,%3}, {%4,%5,%6,%7}, {%8,%9}, {%0,%1,%2,%3};"               \
        : "+f"(C0), "+f"(C1), "+f"(C2), "+f"(C3)                              \
        : "r"(A0), "r"(A1), "r"(A2), "r"(A3), "r"(B0), "r"(B1))

__device__ __forceinline__ void cp16(uint32_t dst, const void* src) {
    asm volatile("cp.async.cg.shared.global [%0], [%1], 16;" :: "r"(dst), "l"(src));
}

// ---------------- all weight transposes in one kernel ------------------------
__global__ void transpose_all(const float* __restrict__ wq,
                              const float* __restrict__ wkv,
                              const float* __restrict__ wout,
                              float* __restrict__ wqt,
                              float* __restrict__ wkvt,
                              float* __restrict__ woutt, float scale) {
    int idx = blockIdx.x * 256 + threadIdx.x;
    if (idx < 16384) {
        int o = idx >> 7, c = idx & 127;
        wqt[c * 128 + o] = wq[idx] * scale;
    } else if (idx < 49152) {
        int i = idx - 16384;
        int o = i >> 7, c = i & 127;
        wkvt[c * 256 + o] = wkv[i];
    } else if (idx < 65536) {
        int i = idx - 49152;
        int o = i >> 7, c = i & 127;
        woutt[c * 128 + o] = wout[i];
    }
}

// ---------------- depthwise 3x3, 4x4 px/thread -------------------------------
template<bool RES, bool BIAS, bool VEC, bool OTF32>
__global__ void dw3q_kernel(const float* __restrict__ in, float* __restrict__ out,
                            const float* __restrict__ w, const float* __restrict__ bias,
                            int H, int W, int cmod) {
    int plane = blockIdx.y;
    int nqx = (W + 3) >> 2, nqy = (H + 3) >> 2;
    int qidx = blockIdx.x * 256 + threadIdx.x;
    if (qidx >= nqx * nqy) return;
    int y0 = (qidx / nqx) << 2, x0 = (qidx % nqx) << 2;
    int c = plane % cmod;
    int HW = H * W;
    const float* ip = in + (size_t)plane * HW;
    const float* wc = w + c * 9;
    float w0[3] = {wc[0], wc[3], wc[6]};
    float w1[3] = {wc[1], wc[4] + (RES ? 1.0f : 0.0f), wc[7]};
    float w2[3] = {wc[2], wc[5], wc[8]};

    float acc[4][4];
    float binit = BIAS ? bias[c] : 0.0f;
#pragma unroll
    for (int r = 0; r < 4; r++)
#pragma unroll
        for (int j = 0; j < 4; j++) acc[r][j] = binit;

    bool xint = (x0 >= 4) && (x0 + 8 <= W);
    bool yint = (y0 >= 1) && (y0 + 5 <= H);
    bool fast = VEC && xint && yint;

    if (fast) {
#pragma unroll
        for (int iy = 0; iy < 6; iy++) {
            const float* rp = ip + (size_t)(y0 + iy - 1) * W;
            float4 mid = *(const float4*)(rp + x0);
            float v0 = rp[x0 - 1], v5 = rp[x0 + 4];
            float v[6] = {v0, mid.x, mid.y, mid.z, mid.w, v5};
#pragma unroll
            for (int r = 0; r < 4; r++) {
                int k = iy - r;
                if (k < 0 || k > 2) continue;
                float wy0 = w0[k], wy1 = w1[k], wy2 = w2[k];
#pragma unroll
                for (int j = 0; j < 4; j++)
                    acc[r][j] += v[j] * wy0 + v[j + 1] * wy1 + v[j + 2] * wy2;
            }
        }
        // vectorized stores (interior => all in bounds)
#pragma unroll
        for (int r = 0; r < 4; r++) {
            float* op = out + (size_t)plane * HW + (size_t)(y0 + r) * W + x0;
            if (OTF32) {
                uint4 u = {f2tf32(acc[r][0]), f2tf32(acc[r][1]),
                           f2tf32(acc[r][2]), f2tf32(acc[r][3])};
                *(uint4*)op = u;
            } else {
                *(float4*)op = make_float4(acc[r][0], acc[r][1], acc[r][2], acc[r][3]);
            }
        }
    } else {
#pragma unroll
        for (int iy = 0; iy < 6; iy++) {
            int yy = y0 + iy - 1;
            if ((unsigned)yy >= (unsigned)H) continue;
            const float* rp = ip + (size_t)yy * W;
            float v[6];
#pragma unroll
            for (int i = 0; i < 6; i++) {
                int xx = x0 - 1 + i;
                v[i] = ((unsigned)xx < (unsigned)W) ? rp[xx] : 0.0f;
            }
#pragma unroll
            for (int r = 0; r < 4; r++) {
                int k = iy - r;
                if (k < 0 || k > 2) continue;
                float wy0 = w0[k], wy1 = w1[k], wy2 = w2[k];
#pragma unroll
                for (int j = 0; j < 4; j++)
                    acc[r][j] += v[j] * wy0 + v[j + 1] * wy1 + v[j + 2] * wy2;
            }
        }
#pragma unroll
        for (int r = 0; r < 4; r++) {
            int yo = y0 + r;
            if (yo >= H) break;
            float* op = out + (size_t)plane * HW + (size_t)yo * W;
#pragma unroll
            for (int j = 0; j < 4; j++) {
                int xo = x0 + j;
                if (xo < W)
                    op[xo] = OTF32 ? __uint_as_float(f2tf32(acc[r][j])) : acc[r][j];
            }
        }
    }
}

// ---------------- reverse gather (overlap-add / count) for fused out-conv ----
__device__ __forceinline__ float rev_load(int b, int c, int p) {
    if (p >= PS_S) return 0.0f;
    int x = p % HS;
    int y = p / HS;
    int wlo = max(0, (y - 2) / 6), whi = min(9, y / 6);
    int vlo = max(0, (x - 2) / 6), vhi = min(9, x / 6);
    float s = 0.0f;
    for (int wh = wlo; wh <= whi; wh++) {
        int dy = y - 6 * wh;
        for (int ww = vlo; ww <= vhi; ww++) {
            int dx = x - 6 * ww;
            int n = wh * 10 + ww;
            s += g_win[((size_t)(b * NWIN + n) * DIM + c) * 64 + dy * 8 + dx];
        }
    }
    int cnt = (whi - wlo + 1) * (vhi - vlo + 1);
    return s / (float)cnt;
}

// ---------------- conv1 as tf32 GEMM, double-buffered, vector staging --------
// REV: X comes from reverse(g_win) instead of `in`.
template<bool REV>
__global__ __launch_bounds__(256, 2)
void conv1_gemm_tf32(const float* __restrict__ Wt, const float* __restrict__ in,
                     float* __restrict__ out, int O, int P) {
    __shared__ uint32_t Ws[2][16][136];
    __shared__ uint32_t Xs[2][16][136];

    int bz = blockIdx.z;
    const float* inb = in + (size_t)bz * 128 * P;
    float* outb = out + (size_t)bz * O * P;

    int p0 = blockIdx.x * 128;
    int o0 = blockIdx.y * 128;
    int tid = threadIdx.x;
    int lane = tid & 31, warp = tid >> 5;
    int wo = warp >> 2;
    int wp = warp & 3;
    int g = lane >> 2;
    int tq = lane & 3;
    int colw = (lane) << 2;     // 0..124
    int krow = warp;            // 0..7

    float c[4][4][4];
#pragma unroll
    for (int mi = 0; mi < 4; mi++)
#pragma unroll
        for (int ni = 0; ni < 4; ni++)
#pragma unroll
            for (int r = 0; r < 4; r++) c[mi][ni][r] = 0.0f;

    float4 wv[2], xv[2];

    auto fetch = [&](int kbase) {
#pragma unroll
        for (int h2 = 0; h2 < 2; h2++) {
            int k = kbase + krow + h2 * 8;
            wv[h2] = *(const float4*)&Wt[(size_t)k * O + o0 + colw];
            int gp = p0 + colw;
            if (REV) {
                xv[h2].x = rev_load(bz, k, gp);
                xv[h2].y = rev_load(bz, k, gp + 1);
                xv[h2].z = rev_load(bz, k, gp + 2);
                xv[h2].w = rev_load(bz, k, gp + 3);
            } else {
                xv[h2] = (gp < P) ? *(const float4*)&inb[(size_t)k * P + gp]
                                  : make_float4(0.f, 0.f, 0.f, 0.f);
            }
        }
    };
    auto stash = [&](int buf) {
#pragma unroll
        for (int h2 = 0; h2 < 2; h2++) {
            int kl = krow + h2 * 8;
            uint4 wu = {f2tf32(wv[h2].x), f2tf32(wv[h2].y), f2tf32(wv[h2].z), f2tf32(wv[h2].w)};
            uint4 xu = {f2tf32(xv[h2].x), f2tf32(xv[h2].y), f2tf32(xv[h2].z), f2tf32(xv[h2].w)};
            *(uint4*)&Ws[buf][kl][colw] = wu;
            *(uint4*)&Xs[buf][kl][colw] = xu;
        }
    };

    fetch(0);
    stash(0);
    __syncthreads();

    for (int kc = 0; kc < 8; kc++) {
        int cur = kc & 1;
        if (kc < 7) fetch((kc + 1) * 16);
#pragma unroll
        for (int s = 0; s < 2; s++) {
            int kb = s * 8;
            uint32_t bf[4][2];
#pragma unroll
            for (int ni = 0; ni < 4; ni++) {
                int col = wp * 32 + ni * 8 + g;
                bf[ni][0] = Xs[cur][kb + tq][col];
                bf[ni][1] = Xs[cur][kb + tq + 4][col];
            }
            uint32_t af[4][4];
#pragma unroll
            for (int mi = 0; mi < 4; mi++) {
                int row = wo * 64 + mi * 16 + g;
                af[mi][0] = Ws[cur][kb + tq][row];
                af[mi][1] = Ws[cur][kb + tq][row + 8];
                af[mi][2] = Ws[cur][kb + tq + 4][row];
                af[mi][3] = Ws[cur][kb + tq + 4][row + 8];
            }
#pragma unroll
            for (int mi = 0; mi < 4; mi++)
#pragma unroll
                for (int ni = 0; ni < 4; ni++)
                    MMA_TF32(c[mi][ni][0], c[mi][ni][1], c[mi][ni][2], c[mi][ni][3],
                             af[mi][0], af[mi][1], af[mi][2], af[mi][3],
                             bf[ni][0], bf[ni][1]);
        }
        if (kc < 7) stash(cur ^ 1);
        __syncthreads();
    }

#pragma unroll
    for (int mi = 0; mi < 4; mi++) {
        int row0 = o0 + wo * 64 + mi * 16 + g;
#pragma unroll
        for (int ni = 0; ni < 4; ni++) {
            int col = p0 + wp * 32 + ni * 8 + 2 * tq;
            if (col + 1 < P) {
                float* r0 = outb + (size_t)row0 * P + col;
                float* r1 = outb + (size_t)(row0 + 8) * P + col;
                r0[0] = c[mi][ni][0]; r0[1] = c[mi][ni][1];
                r1[0] = c[mi][ni][2]; r1[1] = c[mi][ni][3];
            } else {
                if (col < P) {
                    outb[(size_t)row0 * P + col] = c[mi][ni][0];
                    outb[(size_t)(row0 + 8) * P + col] = c[mi][ni][2];
                }
            }
        }
    }
}

// ---------------- windowed attention: cp.async double-buffered K/V -----------
__global__ __launch_bounds__(128)
void attn_mma_kernel() {
    __shared__ uint32_t qs[64][36];
    __shared__ uint32_t ks[2][32][68];
    __shared__ uint32_t vs[2][32][68];

    int bn = blockIdx.x;
    int h  = blockIdx.y;
    int b = bn / NWIN, n = bn % NWIN;
    int wh = n / 10, ww = n % 10;
    int tid = threadIdx.x, lane = tid & 31, warp = tid >> 5;
    int g = lane >> 2, tq = lane & 3;

    int y0q = 6 * wh, x0q = 6 * ww;
    int y0k = 24 * wh, x0k = 24 * ww;

    uint32_t ks_base = (uint32_t)__cvta_generic_to_shared(&ks[0][0][0]);
    uint32_t vs_base = (uint32_t)__cvta_generic_to_shared(&vs[0][0][0]);

    int u_ch[8], u_j[8], u_isv[8];
    const float* srcp[8];
#pragma unroll
    for (int t = 0; t < 8; t++) {
        int u = tid + (t << 7);
        int isv = u >> 9;
        int uu = u & 511;
        int ch = uu >> 4;
        int rem = uu & 15;
        int row = rem >> 3, kx = (rem & 7) << 2;
        u_ch[t] = ch; u_j[t] = (row << 5) + kx; u_isv[t] = isv;
        srcp[t] = g_kv + (((size_t)(b * 2 * DIM + isv * DIM + h * 32 + ch)) * HX
                          + (y0k + row)) * HX + x0k + kx;
    }

#pragma unroll
    for (int t = 0; t < 8; t++) {
        uint32_t dst = (u_isv[t] ? vs_base : ks_base) + (u_ch[t] * 68 + u_j[t]) * 4;
        cp16(dst, srcp[t]);
    }
    asm volatile("cp.async.commit_group;" ::: "memory");

    // stage q (tf32 bits, scale pre-folded) with 8B loads
    const uint32_t* qsrc = (const uint32_t*)g_q;
    for (int e2 = tid; e2 < 1024; e2 += 128) {
        int cch = e2 >> 5;
        int p2 = e2 & 31;
        int i = p2 * 2;
        int dy = i >> 3, dx = i & 7;
        const uint32_t* rowp = qsrc +
            ((size_t)(b * DIM + h * 32 + cch) * HS + y0q + dy) * HS + x0q + dx;
        uint2 v = *(const uint2*)rowp;
        qs[i][cch] = v.x;
        qs[i + 1][cch] = v.y;
    }

    float oacc[4][4];
#pragma unroll
    for (int ni = 0; ni < 4; ni++)
#pragma unroll
        for (int r = 0; r < 4; r++) oacc[ni][r] = 0.0f;
    float mrow0 = -1e30f, mrow1 = -1e30f, lrow0 = 0.0f, lrow1 = 0.0f;

    int m0 = warp * 16;
    int srcl  = (lane & 28) + (tq >> 1);
    int srcl2 = srcl + 2;
    bool odd = (tq & 1);

    for (int i = 0; i < 16; i++) {
        int cur = i & 1;
        if (i < 15) {
            int nb = cur ^ 1;
            int rowoff = (i + 1) * 2 * HX;
#pragma unroll
            for (int t = 0; t < 8; t++) {
                uint32_t dst = (u_isv[t] ? vs_base : ks_base)
                             + ((nb * 32 + u_ch[t]) * 68 + u_j[t]) * 4;
                cp16(dst, srcp[t] + rowoff);
            }
            asm volatile("cp.async.commit_group;" ::: "memory");
            asm volatile("cp.async.wait_group 1;" ::: "memory");
        } else {
            asm volatile("cp.async.wait_group 0;" ::: "memory");
        }
        __syncthreads();

        // ---- S = Q K^T (16 x 64 per warp) ----
        float sc[8][4];
#pragma unroll
        for (int ni = 0; ni < 8; ni++)
#pragma unroll
            for (int r = 0; r < 4; r++) sc[ni][r] = 0.0f;

#pragma unroll
        for (int k0 = 0; k0 < 4; k0++) {
            uint32_t a0 = qs[m0 + g][k0 * 8 + tq];
            uint32_t a1 = qs[m0 + g + 8][k0 * 8 + tq];
            uint32_t a2 = qs[m0 + g][k0 * 8 + tq + 4];
            uint32_t a3 = qs[m0 + g + 8][k0 * 8 + tq + 4];
#pragma unroll
            for (int ni = 0; ni < 8; ni++) {
                uint32_t b0 = ks[cur][k0 * 8 + tq][ni * 8 + g];
                uint32_t b1 = ks[cur][k0 * 8 + tq + 4][ni * 8 + g];
                MMA_TF32(sc[ni][0], sc[ni][1], sc[ni][2], sc[ni][3],
                         a0, a1, a2, a3, b0, b1);
            }
        }

        // ---- streaming softmax ----
        float mx0 = -1e30f, mx1 = -1e30f;
#pragma unroll
        for (int ni = 0; ni < 8; ni++) {
            mx0 = fmaxf(mx0, fmaxf(sc[ni][0], sc[ni][1]));
            mx1 = fmaxf(mx1, fmaxf(sc[ni][2], sc[ni][3]));
        }
#pragma unroll
        for (int off = 1; off <= 2; off <<= 1) {
            mx0 = fmaxf(mx0, __shfl_xor_sync(0xFFFFFFFFu, mx0, off));
            mx1 = fmaxf(mx1, __shfl_xor_sync(0xFFFFFFFFu, mx1, off));
        }
        float mn0 = fmaxf(mrow0, mx0), mn1 = fmaxf(mrow1, mx1);
        float cor0 = __expf(mrow0 - mn0), cor1 = __expf(mrow1 - mn1);
        mrow0 = mn0; mrow1 = mn1;

        float s0 = 0.0f, s1 = 0.0f;
#pragma unroll
        for (int ni = 0; ni < 8; ni++) {
            sc[ni][0] = __expf(sc[ni][0] - mn0);
            sc[ni][1] = __expf(sc[ni][1] - mn0);
            sc[ni][2] = __expf(sc[ni][2] - mn1);
            sc[ni][3] = __expf(sc[ni][3] - mn1);
            s0 += sc[ni][0] + sc[ni][1];
            s1 += sc[ni][2] + sc[ni][3];
        }
#pragma unroll
        for (int off = 1; off <= 2; off <<= 1) {
            s0 += __shfl_xor_sync(0xFFFFFFFFu, s0, off);
            s1 += __shfl_xor_sync(0xFFFFFFFFu, s1, off);
        }
        lrow0 = lrow0 * cor0 + s0;
        lrow1 = lrow1 * cor1 + s1;
#pragma unroll
        for (int ni = 0; ni < 4; ni++) {
            oacc[ni][0] *= cor0; oacc[ni][1] *= cor0;
            oacc[ni][2] *= cor1; oacc[ni][3] *= cor1;
        }

        // ---- O += P V : A-frags via shfl transpose ----
#pragma unroll
        for (int kk = 0; kk < 8; kk++) {
            uint32_t p0 = f2tf32(sc[kk][0]);
            uint32_t p1 = f2tf32(sc[kk][1]);
            uint32_t p2 = f2tf32(sc[kk][2]);
            uint32_t p3 = f2tf32(sc[kk][3]);
            uint32_t q00 = __shfl_sync(0xFFFFFFFFu, p0, srcl);
            uint32_t q10 = __shfl_sync(0xFFFFFFFFu, p1, srcl);
            uint32_t q20 = __shfl_sync(0xFFFFFFFFu, p2, srcl);
            uint32_t q30 = __shfl_sync(0xFFFFFFFFu, p3, srcl);
            uint32_t q01 = __shfl_sync(0xFFFFFFFFu, p0, srcl2);
            uint32_t q11 = __shfl_sync(0xFFFFFFFFu, p1, srcl2);
            uint32_t q21 = __shfl_sync(0xFFFFFFFFu, p2, srcl2);
            uint32_t q31 = __shfl_sync(0xFFFFFFFFu, p3, srcl2);
            uint32_t a0 = odd ? q10 : q00;
            uint32_t a1 = odd ? q30 : q20;
            uint32_t a2 = odd ? q11 : q01;
            uint32_t a3 = odd ? q31 : q21;
#pragma unroll
            for (int ni = 0; ni < 4; ni++) {
                uint32_t b0 = vs[cur][ni * 8 + g][kk * 8 + tq];
                uint32_t b1 = vs[cur][ni * 8 + g][kk * 8 + tq + 4];
                MMA_TF32(oacc[ni][0], oacc[ni][1], oacc[ni][2], oacc[ni][3],
                         a0, a1, a2, a3, b0, b1);
            }
        }
        __syncthreads();
    }

    float inv0 = 1.0f / lrow0, inv1 = 1.0f / lrow1;
#pragma unroll
    for (int ni = 0; ni < 4; ni++) {
        int col = h * 32 + ni * 8 + 2 * tq;
        size_t base = (size_t)bn * DIM;
        g_win[(base + col) * 64 + m0 + g]         = oacc[ni][0] * inv0;
        g_win[(base + col + 1) * 64 + m0 + g]     = oacc[ni][1] * inv0;
        g_win[(base + col) * 64 + m0 + g + 8]     = oacc[ni][2] * inv1;
        g_win[(base + col + 1) * 64 + m0 + g + 8] = oacc[ni][3] * inv1;
    }
}

// ---------------- launch -----------------------------------------------------
extern "C" void kernel_launch(void* const* d_in, const int* in_sizes, int n_in,
                              void* d_out, int out_size) {
    const float* x     = (const float*)d_in[0];
    const float* sp    = (const float*)d_in[1];
    const float* w_pos = (const float*)d_in[2];
    const float* b_pos = (const float*)d_in[3];
    const float* w_q   = (const float*)d_in[4];
    const float* w_qdw = (const float*)d_in[5];
    const float* w_kv  = (const float*)d_in[6];
    const float* w_kvdw= (const float*)d_in[7];
    const float* w_out = (const float*)d_in[8];
    float* out = (float*)d_out;

    float *xp, *spp, *tkv, *kv, *tq, *q, *wq_t, *wkv_t, *wout_t;
    cudaGetSymbolAddress((void**)&xp,    g_xp);
    cudaGetSymbolAddress((void**)&spp,   g_spp);
    cudaGetSymbolAddress((void**)&tkv,   g_tkv);
    cudaGetSymbolAddress((void**)&kv,    g_kv);
    cudaGetSymbolAddress((void**)&tq,    g_tq);
    cudaGetSymbolAddress((void**)&q,     g_q);
    cudaGetSymbolAddress((void**)&wq_t,  g_wq_t);
    cudaGetSymbolAddress((void**)&wkv_t, g_wkv_t);
    cudaGetSymbolAddress((void**)&wout_t,g_wout_t);

    const float scale = 0.17677669529663687f; // 1/sqrt(32), folded into w_q
    transpose_all<<<256, 256>>>(w_q, w_kv, w_out, wq_t, wkv_t, wout_t, scale);

    int nqx = ((HX + 3) / 4) * ((HX + 3) / 4);
    int nqs = ((HS + 3) / 4) * ((HS + 3) / 4);

    // pos convs (residual folded into center tap; bias)
    dw3q_kernel<true, true, true, false><<<dim3((nqx + 255)/256, BATCH*DIM), 256>>>(
        x, xp, w_pos, b_pos, HX, HX, DIM);
    dw3q_kernel<true, true, false, false><<<dim3((nqs + 255)/256, BATCH*DIM), 256>>>(
        sp, spp, w_pos, b_pos, HS, HS, DIM);

    // q path (output tf32-rounded for attention)
    conv1_gemm_tf32<false><<<dim3((PS_S + 127)/128, 1, BATCH), 256>>>(wq_t, spp, tq, DIM, PS_S);
    dw3q_kernel<false, false, false, true><<<dim3((nqs + 255)/256, BATCH*DIM), 256>>>(
        tq, q, w_qdw, nullptr, HS, HS, DIM);

    // kv path (output tf32-rounded for attention)
    conv1_gemm_tf32<false><<<dim3((PS_X + 127)/128, 2, BATCH), 256>>>(wkv_t, xp, tkv, 2*DIM, PS_X);
    dw3q_kernel<false, false, true, true><<<dim3((nqx + 255)/256, BATCH*2*DIM), 256>>>(
        tkv, kv, w_kvdw, nullptr, HX, HX, 2*DIM);

    attn_mma_kernel<<<dim3(BATCH*NWIN, 4), 128>>>();

    // final conv1 with reverse fused into X staging
    conv1_gemm_tf32<true><<<dim3((PS_S + 127)/128, 1, BATCH), 256>>>(wout_t, nullptr, out, DIM, PS_S);
}

// round 8
// speedup vs baseline: 1.0775x; 1.0775x over previous
#include <cuda_runtime.h>
#include <cstdint>

#define BATCH 2
#define DIM   128
#define HS    62
#define HX    248
#define PS_S  (HS*HS)   // 3844
#define PS_X  (HX*HX)   // 61504
#define NWIN  100       // 10x10 windows

// ---------------- scratch ----------------------------------------------------
__device__ float g_xp  [BATCH*DIM*PS_X];
__device__ float g_spp [BATCH*DIM*PS_S];
__device__ float g_tkv [BATCH*2*DIM*PS_X];
__device__ float g_kv  [BATCH*2*DIM*PS_X];   // tf32-rounded values
__device__ float g_tq  [BATCH*DIM*PS_S];
__device__ float g_q   [BATCH*DIM*PS_S];     // tf32-rounded, scale folded
__device__ float g_win [BATCH*NWIN*DIM*64];
__device__ float g_acc [BATCH*DIM*PS_S];
__device__ float g_wq_t  [DIM*DIM];
__device__ float g_wkv_t [DIM*2*DIM];
__device__ float g_wout_t[DIM*DIM];

__device__ __forceinline__ uint32_t f2tf32(float f) {
    uint32_t u;
    asm("cvt.rna.tf32.f32 %0, %1;" : "=r"(u) : "f"(f));
    return u;
}

#define MMA_TF32(C0,C1,C2,C3,A0,A1,A2,A3,B0,B1)                               \
    asm volatile(                                                             \
        "mma.sync.aligned.m16n8k8.row.col.f32.tf32.tf32.f32 "                 \
        "{%0,%1,%2,%3}, {%4,%5,%6,%7}, {%8,%9}, {%0,%1,%2,%3};"               \
        : "+f"(C0), "+f"(C1), "+f"(C2), "+f"(C3)                              \
        : "r"(A0), "r"(A1), "r"(A2), "r"(A3), "r"(B0), "r"(B1))

__device__ __forceinline__ void cp16(uint32_t dst, const void* src) {
    asm volatile("cp.async.cg.shared.global [%0], [%1], 16;" :: "r"(dst), "l"(src));
}

// ---------------- all weight transposes in one kernel ------------------------
__global__ void transpose_all(const float* __restrict__ wq,
                              const float* __restrict__ wkv,
                              const float* __restrict__ wout,
                              float* __restrict__ wqt,
                              float* __restrict__ wkvt,
                              float* __restrict__ woutt, float scale) {
    int idx = blockIdx.x * 256 + threadIdx.x;
    if (idx < 16384) {
        int o = idx >> 7, c = idx & 127;
        wqt[c * 128 + o] = wq[idx] * scale;
    } else if (idx < 49152) {
        int i = idx - 16384;
        int o = i >> 7, c = i & 127;
        wkvt[c * 256 + o] = wkv[i];
    } else if (idx < 65536) {
        int i = idx - 49152;
        int o = i >> 7, c = i & 127;
        woutt[c * 128 + o] = wout[i];
    }
}

// ---------------- depthwise 3x3, 4x4 px/thread -------------------------------
template<bool RES, bool BIAS, bool VEC, bool OTF32>
__global__ void dw3q_kernel(const float* __restrict__ in, float* __restrict__ out,
                            const float* __restrict__ w, const float* __restrict__ bias,
                            int H, int W, int cmod) {
    int plane = blockIdx.y;
    int nqx = (W + 3) >> 2, nqy = (H + 3) >> 2;
    int qidx = blockIdx.x * 256 + threadIdx.x;
    if (qidx >= nqx * nqy) return;
    int y0 = (qidx / nqx) << 2, x0 = (qidx % nqx) << 2;
    int c = plane % cmod;
    int HW = H * W;
    const float* ip = in + (size_t)plane * HW;
    const float* wc = w + c * 9;
    float w0[3] = {wc[0], wc[3], wc[6]};
    float w1[3] = {wc[1], wc[4] + (RES ? 1.0f : 0.0f), wc[7]};
    float w2[3] = {wc[2], wc[5], wc[8]};

    float acc[4][4];
    float binit = BIAS ? bias[c] : 0.0f;
#pragma unroll
    for (int r = 0; r < 4; r++)
#pragma unroll
        for (int j = 0; j < 4; j++) acc[r][j] = binit;

    bool xint = (x0 >= 4) && (x0 + 8 <= W);
    bool yint = (y0 >= 1) && (y0 + 5 <= H);
    bool fast = VEC && xint && yint;

    if (fast) {
#pragma unroll
        for (int iy = 0; iy < 6; iy++) {
            const float* rp = ip + (size_t)(y0 + iy - 1) * W;
            float4 mid = *(const float4*)(rp + x0);
            float v0 = rp[x0 - 1], v5 = rp[x0 + 4];
            float v[6] = {v0, mid.x, mid.y, mid.z, mid.w, v5};
#pragma unroll
            for (int r = 0; r < 4; r++) {
                int k = iy - r;
                if (k < 0 || k > 2) continue;
                float wy0 = w0[k], wy1 = w1[k], wy2 = w2[k];
#pragma unroll
                for (int j = 0; j < 4; j++)
                    acc[r][j] += v[j] * wy0 + v[j + 1] * wy1 + v[j + 2] * wy2;
            }
        }
#pragma unroll
        for (int r = 0; r < 4; r++) {
            float* op = out + (size_t)plane * HW + (size_t)(y0 + r) * W + x0;
            if (OTF32) {
                uint4 u = {f2tf32(acc[r][0]), f2tf32(acc[r][1]),
                           f2tf32(acc[r][2]), f2tf32(acc[r][3])};
                *(uint4*)op = u;
            } else {
                *(float4*)op = make_float4(acc[r][0], acc[r][1], acc[r][2], acc[r][3]);
            }
        }
    } else {
#pragma unroll
        for (int iy = 0; iy < 6; iy++) {
            int yy = y0 + iy - 1;
            if ((unsigned)yy >= (unsigned)H) continue;
            const float* rp = ip + (size_t)yy * W;
            float v[6];
#pragma unroll
            for (int i = 0; i < 6; i++) {
                int xx = x0 - 1 + i;
                v[i] = ((unsigned)xx < (unsigned)W) ? rp[xx] : 0.0f;
            }
#pragma unroll
            for (int r = 0; r < 4; r++) {
                int k = iy - r;
                if (k < 0 || k > 2) continue;
                float wy0 = w0[k], wy1 = w1[k], wy2 = w2[k];
#pragma unroll
                for (int j = 0; j < 4; j++)
                    acc[r][j] += v[j] * wy0 + v[j + 1] * wy1 + v[j + 2] * wy2;
            }
        }
#pragma unroll
        for (int r = 0; r < 4; r++) {
            int yo = y0 + r;
            if (yo >= H) break;
            float* op = out + (size_t)plane * HW + (size_t)yo * W;
#pragma unroll
            for (int j = 0; j < 4; j++) {
                int xo = x0 + j;
                if (xo < W)
                    op[xo] = OTF32 ? __uint_as_float(f2tf32(acc[r][j])) : acc[r][j];
            }
        }
    }
}

// ---------------- conv1 as tf32 GEMM, double-buffered, 1 sync/chunk ----------
// (round-6 proven version: scalar staging, low register pressure)
__global__ __launch_bounds__(256, 2)
void conv1_gemm_tf32(const float* __restrict__ Wt, const float* __restrict__ in,
                     float* __restrict__ out, int O, int P) {
    __shared__ uint32_t Ws[2][16][136];
    __shared__ uint32_t Xs[2][16][136];

    const float* inb = in + (size_t)blockIdx.z * 128 * P;
    float* outb = out + (size_t)blockIdx.z * O * P;

    int p0 = blockIdx.x * 128;
    int o0 = blockIdx.y * 128;
    int tid = threadIdx.x;
    int lane = tid & 31, warp = tid >> 5;
    int wo = warp >> 2;
    int wp = warp & 3;
    int g = lane >> 2;
    int tq = lane & 3;

    float c[4][4][4];
#pragma unroll
    for (int mi = 0; mi < 4; mi++)
#pragma unroll
        for (int ni = 0; ni < 4; ni++)
#pragma unroll
            for (int r = 0; r < 4; r++) c[mi][ni][r] = 0.0f;

    float wr[8], xr[8];
#pragma unroll
    for (int l = 0; l < 8; l++) {
        int e = tid + l * 256;
        int k = e >> 7, o = e & 127;
        wr[l] = Wt[(size_t)k * O + o0 + o];
        int gp = p0 + o;
        xr[l] = (gp < P) ? inb[(size_t)k * P + gp] : 0.0f;
    }
#pragma unroll
    for (int l = 0; l < 8; l++) {
        int e = tid + l * 256;
        int k = e >> 7, o = e & 127;
        Ws[0][k][o] = f2tf32(wr[l]);
        Xs[0][k][o] = f2tf32(xr[l]);
    }
    __syncthreads();

    for (int kc = 0; kc < 8; kc++) {
        int cur = kc & 1;
        if (kc < 7) {
            int kbase = (kc + 1) * 16;
#pragma unroll
            for (int l = 0; l < 8; l++) {
                int e = tid + l * 256;
                int k = e >> 7, o = e & 127;
                wr[l] = Wt[(size_t)(kbase + k) * O + o0 + o];
                int gp = p0 + o;
                xr[l] = (gp < P) ? inb[(size_t)(kbase + k) * P + gp] : 0.0f;
            }
        }
#pragma unroll
        for (int s = 0; s < 2; s++) {
            int kb = s * 8;
            uint32_t bf[4][2];
#pragma unroll
            for (int ni = 0; ni < 4; ni++) {
                int col = wp * 32 + ni * 8 + g;
                bf[ni][0] = Xs[cur][kb + tq][col];
                bf[ni][1] = Xs[cur][kb + tq + 4][col];
            }
            uint32_t af[4][4];
#pragma unroll
            for (int mi = 0; mi < 4; mi++) {
                int row = wo * 64 + mi * 16 + g;
                af[mi][0] = Ws[cur][kb + tq][row];
                af[mi][1] = Ws[cur][kb + tq][row + 8];
                af[mi][2] = Ws[cur][kb + tq + 4][row];
                af[mi][3] = Ws[cur][kb + tq + 4][row + 8];
            }
#pragma unroll
            for (int mi = 0; mi < 4; mi++)
#pragma unroll
                for (int ni = 0; ni < 4; ni++)
                    MMA_TF32(c[mi][ni][0], c[mi][ni][1], c[mi][ni][2], c[mi][ni][3],
                             af[mi][0], af[mi][1], af[mi][2], af[mi][3],
                             bf[ni][0], bf[ni][1]);
        }
        if (kc < 7) {
            int nb = cur ^ 1;
#pragma unroll
            for (int l = 0; l < 8; l++) {
                int e = tid + l * 256;
                int k = e >> 7, o = e & 127;
                Ws[nb][k][o] = f2tf32(wr[l]);
                Xs[nb][k][o] = f2tf32(xr[l]);
            }
        }
        __syncthreads();
    }

#pragma unroll
    for (int mi = 0; mi < 4; mi++) {
        int row0 = o0 + wo * 64 + mi * 16 + g;
#pragma unroll
        for (int ni = 0; ni < 4; ni++) {
            int col = p0 + wp * 32 + ni * 8 + 2 * tq;
            if (col + 1 < P) {
                float* r0 = outb + (size_t)row0 * P + col;
                float* r1 = outb + (size_t)(row0 + 8) * P + col;
                r0[0] = c[mi][ni][0]; r0[1] = c[mi][ni][1];
                r1[0] = c[mi][ni][2]; r1[1] = c[mi][ni][3];
            } else {
                if (col < P) {
                    outb[(size_t)row0 * P + col] = c[mi][ni][0];
                    outb[(size_t)(row0 + 8) * P + col] = c[mi][ni][2];
                }
            }
        }
    }
}

// ---------------- windowed attention: cp.async double-buffered K/V -----------
__global__ __launch_bounds__(128)
void attn_mma_kernel() {
    __shared__ uint32_t qs[64][36];
    __shared__ uint32_t ks[2][32][68];
    __shared__ uint32_t vs[2][32][68];

    int bn = blockIdx.x;
    int h  = blockIdx.y;
    int b = bn / NWIN, n = bn % NWIN;
    int wh = n / 10, ww = n % 10;
    int tid = threadIdx.x, lane = tid & 31, warp = tid >> 5;
    int g = lane >> 2, tq = lane & 3;

    int y0q = 6 * wh, x0q = 6 * ww;
    int y0k = 24 * wh, x0k = 24 * ww;

    uint32_t ks_base = (uint32_t)__cvta_generic_to_shared(&ks[0][0][0]);
    uint32_t vs_base = (uint32_t)__cvta_generic_to_shared(&vs[0][0][0]);

    int u_ch[8], u_j[8], u_isv[8];
    const float* srcp[8];
#pragma unroll
    for (int t = 0; t < 8; t++) {
        int u = tid + (t << 7);
        int isv = u >> 9;
        int uu = u & 511;
        int ch = uu >> 4;
        int rem = uu & 15;
        int row = rem >> 3, kx = (rem & 7) << 2;
        u_ch[t] = ch; u_j[t] = (row << 5) + kx; u_isv[t] = isv;
        srcp[t] = g_kv + (((size_t)(b * 2 * DIM + isv * DIM + h * 32 + ch)) * HX
                          + (y0k + row)) * HX + x0k + kx;
    }

#pragma unroll
    for (int t = 0; t < 8; t++) {
        uint32_t dst = (u_isv[t] ? vs_base : ks_base) + (u_ch[t] * 68 + u_j[t]) * 4;
        cp16(dst, srcp[t]);
    }
    asm volatile("cp.async.commit_group;" ::: "memory");

    // stage q (tf32 bits, scale pre-folded) with 8B loads
    const uint32_t* qsrc = (const uint32_t*)g_q;
    for (int e2 = tid; e2 < 1024; e2 += 128) {
        int cch = e2 >> 5;
        int p2 = e2 & 31;
        int i = p2 * 2;
        int dy = i >> 3, dx = i & 7;
        const uint32_t* rowp = qsrc +
            ((size_t)(b * DIM + h * 32 + cch) * HS + y0q + dy) * HS + x0q + dx;
        uint2 v = *(const uint2*)rowp;
        qs[i][cch] = v.x;
        qs[i + 1][cch] = v.y;
    }

    float oacc[4][4];
#pragma unroll
    for (int ni = 0; ni < 4; ni++)
#pragma unroll
        for (int r = 0; r < 4; r++) oacc[ni][r] = 0.0f;
    float mrow0 = -1e30f, mrow1 = -1e30f, lrow0 = 0.0f, lrow1 = 0.0f;

    int m0 = warp * 16;
    int srcl  = (lane & 28) + (tq >> 1);
    int srcl2 = srcl + 2;
    bool odd = (tq & 1);

    for (int i = 0; i < 16; i++) {
        int cur = i & 1;
        if (i < 15) {
            int nb = cur ^ 1;
            int rowoff = (i + 1) * 2 * HX;
#pragma unroll
            for (int t = 0; t < 8; t++) {
                uint32_t dst = (u_isv[t] ? vs_base : ks_base)
                             + ((nb * 32 + u_ch[t]) * 68 + u_j[t]) * 4;
                cp16(dst, srcp[t] + rowoff);
            }
            asm volatile("cp.async.commit_group;" ::: "memory");
            asm volatile("cp.async.wait_group 1;" ::: "memory");
        } else {
            asm volatile("cp.async.wait_group 0;" ::: "memory");
        }
        __syncthreads();

        // ---- S = Q K^T (16 x 64 per warp) ----
        float sc[8][4];
#pragma unroll
        for (int ni = 0; ni < 8; ni++)
#pragma unroll
            for (int r = 0; r < 4; r++) sc[ni][r] = 0.0f;

#pragma unroll
        for (int k0 = 0; k0 < 4; k0++) {
            uint32_t a0 = qs[m0 + g][k0 * 8 + tq];
            uint32_t a1 = qs[m0 + g + 8][k0 * 8 + tq];
            uint32_t a2 = qs[m0 + g][k0 * 8 + tq + 4];
            uint32_t a3 = qs[m0 + g + 8][k0 * 8 + tq + 4];
#pragma unroll
            for (int ni = 0; ni < 8; ni++) {
                uint32_t b0 = ks[cur][k0 * 8 + tq][ni * 8 + g];
                uint32_t b1 = ks[cur][k0 * 8 + tq + 4][ni * 8 + g];
                MMA_TF32(sc[ni][0], sc[ni][1], sc[ni][2], sc[ni][3],
                         a0, a1, a2, a3, b0, b1);
            }
        }

        // ---- streaming softmax ----
        float mx0 = -1e30f, mx1 = -1e30f;
#pragma unroll
        for (int ni = 0; ni < 8; ni++) {
            mx0 = fmaxf(mx0, fmaxf(sc[ni][0], sc[ni][1]));
            mx1 = fmaxf(mx1, fmaxf(sc[ni][2], sc[ni][3]));
        }
#pragma unroll
        for (int off = 1; off <= 2; off <<= 1) {
            mx0 = fmaxf(mx0, __shfl_xor_sync(0xFFFFFFFFu, mx0, off));
            mx1 = fmaxf(mx1, __shfl_xor_sync(0xFFFFFFFFu, mx1, off));
        }
        float mn0 = fmaxf(mrow0, mx0), mn1 = fmaxf(mrow1, mx1);
        float cor0 = __expf(mrow0 - mn0), cor1 = __expf(mrow1 - mn1);
        mrow0 = mn0; mrow1 = mn1;

        float s0 = 0.0f, s1 = 0.0f;
#pragma unroll
        for (int ni = 0; ni < 8; ni++) {
            sc[ni][0] = __expf(sc[ni][0] - mn0);
            sc[ni][1] = __expf(sc[ni][1] - mn0);
            sc[ni][2] = __expf(sc[ni][2] - mn1);
            sc[ni][3] = __expf(sc[ni][3] - mn1);
            s0 += sc[ni][0] + sc[ni][1];
            s1 += sc[ni][2] + sc[ni][3];
        }
#pragma unroll
        for (int off = 1; off <= 2; off <<= 1) {
            s0 += __shfl_xor_sync(0xFFFFFFFFu, s0, off);
            s1 += __shfl_xor_sync(0xFFFFFFFFu, s1, off);
        }
        lrow0 = lrow0 * cor0 + s0;
        lrow1 = lrow1 * cor1 + s1;
#pragma unroll
        for (int ni = 0; ni < 4; ni++) {
            oacc[ni][0] *= cor0; oacc[ni][1] *= cor0;
            oacc[ni][2] *= cor1; oacc[ni][3] *= cor1;
        }

        // ---- O += P V : A-frags via shfl transpose ----
#pragma unroll
        for (int kk = 0; kk < 8; kk++) {
            uint32_t p0 = f2tf32(sc[kk][0]);
            uint32_t p1 = f2tf32(sc[kk][1]);
            uint32_t p2 = f2tf32(sc[kk][2]);
            uint32_t p3 = f2tf32(sc[kk][3]);
            uint32_t q00 = __shfl_sync(0xFFFFFFFFu, p0, srcl);
            uint32_t q10 = __shfl_sync(0xFFFFFFFFu, p1, srcl);
            uint32_t q20 = __shfl_sync(0xFFFFFFFFu, p2, srcl);
            uint32_t q30 = __shfl_sync(0xFFFFFFFFu, p3, srcl);
            uint32_t q01 = __shfl_sync(0xFFFFFFFFu, p0, srcl2);
            uint32_t q11 = __shfl_sync(0xFFFFFFFFu, p1, srcl2);
            uint32_t q21 = __shfl_sync(0xFFFFFFFFu, p2, srcl2);
            uint32_t q31 = __shfl_sync(0xFFFFFFFFu, p3, srcl2);
            uint32_t a0 = odd ? q10 : q00;
            uint32_t a1 = odd ? q30 : q20;
            uint32_t a2 = odd ? q11 : q01;
            uint32_t a3 = odd ? q31 : q21;
#pragma unroll
            for (int ni = 0; ni < 4; ni++) {
                uint32_t b0 = vs[cur][ni * 8 + g][kk * 8 + tq];
                uint32_t b1 = vs[cur][ni * 8 + g][kk * 8 + tq + 4];
                MMA_TF32(oacc[ni][0], oacc[ni][1], oacc[ni][2], oacc[ni][3],
                         a0, a1, a2, a3, b0, b1);
            }
        }
        __syncthreads();
    }

    float inv0 = 1.0f / lrow0, inv1 = 1.0f / lrow1;
#pragma unroll
    for (int ni = 0; ni < 4; ni++) {
        int col = h * 32 + ni * 8 + 2 * tq;
        size_t base = (size_t)bn * DIM;
        g_win[(base + col) * 64 + m0 + g]         = oacc[ni][0] * inv0;
        g_win[(base + col + 1) * 64 + m0 + g]     = oacc[ni][1] * inv0;
        g_win[(base + col) * 64 + m0 + g + 8]     = oacc[ni][2] * inv1;
        g_win[(base + col + 1) * 64 + m0 + g + 8] = oacc[ni][3] * inv1;
    }
}

// ---------------- reverse (overlap-add with count normalization) -------------
// 2 horizontally-adjacent pixels per thread (same window set when interior).
__global__ void reverse_kernel() {
    int idx = blockIdx.x * 256 + threadIdx.x;
    int half = BATCH * DIM * PS_S / 2;
    if (idx >= half + (BATCH * DIM * PS_S & 1)) return;
    int base2 = idx * 2;
    int x = base2 % HS;
    int y = (base2 / HS) % HS;
    int c = (base2 / PS_S) % DIM;
    int b = base2 / (PS_S * DIM);

    float o[2];
#pragma unroll
    for (int t = 0; t < 2; t++) {
        int xx = x + t;
        float s = 0.0f;
        int cnt = 0;
        if (xx < HS) {
            int wlo = max(0, (y - 2) / 6), whi = min(9, y / 6);
            int vlo = max(0, (xx - 2) / 6), vhi = min(9, xx / 6);
            for (int wh = wlo; wh <= whi; wh++) {
                int dy = y - 6 * wh;
                for (int ww = vlo; ww <= vhi; ww++) {
                    int dx = xx - 6 * ww;
                    int n = wh * 10 + ww;
                    s += g_win[((size_t)(b * NWIN + n) * DIM + c) * 64 + dy * 8 + dx];
                }
            }
            cnt = (whi - wlo + 1) * (vhi - vlo + 1);
        }
        o[t] = cnt ? s / (float)cnt : 0.0f;
    }
    float* op = g_acc + (size_t)base2;
    op[0] = o[0];
    if (x + 1 < HS) op[1] = o[1];
}

// ---------------- launch -----------------------------------------------------
extern "C" void kernel_launch(void* const* d_in, const int* in_sizes, int n_in,
                              void* d_out, int out_size) {
    const float* x     = (const float*)d_in[0];
    const float* sp    = (const float*)d_in[1];
    const float* w_pos = (const float*)d_in[2];
    const float* b_pos = (const float*)d_in[3];
    const float* w_q   = (const float*)d_in[4];
    const float* w_qdw = (const float*)d_in[5];
    const float* w_kv  = (const float*)d_in[6];
    const float* w_kvdw= (const float*)d_in[7];
    const float* w_out = (const float*)d_in[8];
    float* out = (float*)d_out;

    float *xp, *spp, *tkv, *kv, *tq, *q, *acc, *wq_t, *wkv_t, *wout_t;
    cudaGetSymbolAddress((void**)&xp,    g_xp);
    cudaGetSymbolAddress((void**)&spp,   g_spp);
    cudaGetSymbolAddress((void**)&tkv,   g_tkv);
    cudaGetSymbolAddress((void**)&kv,    g_kv);
    cudaGetSymbolAddress((void**)&tq,    g_tq);
    cudaGetSymbolAddress((void**)&q,     g_q);
    cudaGetSymbolAddress((void**)&acc,   g_acc);
    cudaGetSymbolAddress((void**)&wq_t,  g_wq_t);
    cudaGetSymbolAddress((void**)&wkv_t, g_wkv_t);
    cudaGetSymbolAddress((void**)&wout_t,g_wout_t);

    const float scale = 0.17677669529663687f; // 1/sqrt(32), folded into w_q
    transpose_all<<<256, 256>>>(w_q, w_kv, w_out, wq_t, wkv_t, wout_t, scale);

    int nqx = ((HX + 3) / 4) * ((HX + 3) / 4);
    int nqs = ((HS + 3) / 4) * ((HS + 3) / 4);

    dw3q_kernel<true, true, true, false><<<dim3((nqx + 255)/256, BATCH*DIM), 256>>>(
        x, xp, w_pos, b_pos, HX, HX, DIM);
    dw3q_kernel<true, true, false, false><<<dim3((nqs + 255)/256, BATCH*DIM), 256>>>(
        sp, spp, w_pos, b_pos, HS, HS, DIM);

    conv1_gemm_tf32<<<dim3((PS_S + 127)/128, 1, BATCH), 256>>>(wq_t, spp, tq, DIM, PS_S);
    dw3q_kernel<false, false, false, true><<<dim3((nqs + 255)/256, BATCH*DIM), 256>>>(
        tq, q, w_qdw, nullptr, HS, HS, DIM);

    conv1_gemm_tf32<<<dim3((PS_X + 127)/128, 2, BATCH), 256>>>(wkv_t, xp, tkv, 2*DIM, PS_X);
    dw3q_kernel<false, false, true, true><<<dim3((nqx + 255)/256, BATCH*2*DIM), 256>>>(
        tkv, kv, w_kvdw, nullptr, HX, HX, 2*DIM);

    attn_mma_kernel<<<dim3(BATCH*NWIN, 4), 128>>>();

    reverse_kernel<<<(BATCH*DIM*PS_S/2 + 255)/256, 256>>>();

    conv1_gemm_tf32<<<dim3((PS_S + 127)/128, 1, BATCH), 256>>>(wout_t, acc, out, DIM, PS_S);
}

// round 9
// speedup vs baseline: 1.1672x; 1.0833x over previous
#include <cuda_runtime.h>
#include <cstdint>

#define BATCH 2
#define DIM   128
#define HS    62
#define HX    248
#define PS_S  (HS*HS)   // 3844
#define PS_X  (HX*HX)   // 61504
#define NWIN  100       // 10x10 windows

// ---------------- scratch ----------------------------------------------------
__device__ float g_xp  [BATCH*DIM*PS_X];
__device__ float g_spp [BATCH*DIM*PS_S];
__device__ float g_tkv [BATCH*2*DIM*PS_X];
__device__ float g_kv  [BATCH*2*DIM*PS_X];   // tf32-rounded values
__device__ float g_tq  [BATCH*DIM*PS_S];
__device__ float g_q   [BATCH*DIM*PS_S];     // tf32-rounded, scale*log2e folded
__device__ float g_win [BATCH*NWIN*DIM*64];
__device__ float g_acc [BATCH*DIM*PS_S];
__device__ float g_wq_t  [DIM*DIM];
__device__ float g_wkv_t [DIM*2*DIM];
__device__ float g_wout_t[DIM*DIM];

__device__ __forceinline__ uint32_t f2tf32(float f) {
    uint32_t u;
    asm("cvt.rna.tf32.f32 %0, %1;" : "=r"(u) : "f"(f));
    return u;
}
__device__ __forceinline__ float ex2(float x) {
    float y;
    asm("ex2.approx.f32 %0, %1;" : "=f"(y) : "f"(x));
    return y;
}

#define MMA_TF32(C0,C1,C2,C3,A0,A1,A2,A3,B0,B1)                               \
    asm volatile(                                                             \
        "mma.sync.aligned.m16n8k8.row.col.f32.tf32.tf32.f32 "                 \
        "{%0,%1,%2,%3}, {%4,%5,%6,%7}, {%8,%9}, {%0,%1,%2,%3};"               \
        : "+f"(C0), "+f"(C1), "+f"(C2), "+f"(C3)                              \
        : "r"(A0), "r"(A1), "r"(A2), "r"(A3), "r"(B0), "r"(B1))

__device__ __forceinline__ void cp16(uint32_t dst, const void* src) {
    asm volatile("cp.async.cg.shared.global [%0], [%1], 16;" :: "r"(dst), "l"(src));
}

// ---------------- all weight transposes in one kernel ------------------------
__global__ void transpose_all(const float* __restrict__ wq,
                              const float* __restrict__ wkv,
                              const float* __restrict__ wout,
                              float* __restrict__ wqt,
                              float* __restrict__ wkvt,
                              float* __restrict__ woutt, float scale) {
    int idx = blockIdx.x * 256 + threadIdx.x;
    if (idx < 16384) {
        int o = idx >> 7, c = idx & 127;
        wqt[c * 128 + o] = wq[idx] * scale;
    } else if (idx < 49152) {
        int i = idx - 16384;
        int o = i >> 7, c = i & 127;
        wkvt[c * 256 + o] = wkv[i];
    } else if (idx < 65536) {
        int i = idx - 49152;
        int o = i >> 7, c = i & 127;
        woutt[c * 128 + o] = wout[i];
    }
}

// ---------------- depthwise 3x3 core (4x4 px/thread) -------------------------
__device__ __forceinline__ void dw3_core(const float* __restrict__ ip,
                                         float* __restrict__ opb,
                                         int H, int W,
                                         const float* __restrict__ wc,
                                         float centerAdd, float binit,
                                         bool vec, bool otf32,
                                         int y0, int x0) {
    float w0[3] = {wc[0], wc[3], wc[6]};
    float w1[3] = {wc[1], wc[4] + centerAdd, wc[7]};
    float w2[3] = {wc[2], wc[5], wc[8]};

    float acc[4][4];
#pragma unroll
    for (int r = 0; r < 4; r++)
#pragma unroll
        for (int j = 0; j < 4; j++) acc[r][j] = binit;

    bool xint = (x0 >= 4) && (x0 + 8 <= W);
    bool yint = (y0 >= 1) && (y0 + 5 <= H);

    if (vec && xint && yint) {
#pragma unroll
        for (int iy = 0; iy < 6; iy++) {
            const float* rp = ip + (size_t)(y0 + iy - 1) * W;
            float4 mid = *(const float4*)(rp + x0);
            float v0 = rp[x0 - 1], v5 = rp[x0 + 4];
            float v[6] = {v0, mid.x, mid.y, mid.z, mid.w, v5};
#pragma unroll
            for (int r = 0; r < 4; r++) {
                int k = iy - r;
                if (k < 0 || k > 2) continue;
                float wy0 = w0[k], wy1 = w1[k], wy2 = w2[k];
#pragma unroll
                for (int j = 0; j < 4; j++)
                    acc[r][j] += v[j] * wy0 + v[j + 1] * wy1 + v[j + 2] * wy2;
            }
        }
#pragma unroll
        for (int r = 0; r < 4; r++) {
            float* op = opb + (size_t)(y0 + r) * W + x0;
            if (otf32) {
                uint4 u = {f2tf32(acc[r][0]), f2tf32(acc[r][1]),
                           f2tf32(acc[r][2]), f2tf32(acc[r][3])};
                *(uint4*)op = u;
            } else {
                *(float4*)op = make_float4(acc[r][0], acc[r][1], acc[r][2], acc[r][3]);
            }
        }
    } else {
#pragma unroll
        for (int iy = 0; iy < 6; iy++) {
            int yy = y0 + iy - 1;
            if ((unsigned)yy >= (unsigned)H) continue;
            const float* rp = ip + (size_t)yy * W;
            float v[6];
#pragma unroll
            for (int i = 0; i < 6; i++) {
                int xx = x0 - 1 + i;
                v[i] = ((unsigned)xx < (unsigned)W) ? rp[xx] : 0.0f;
            }
#pragma unroll
            for (int r = 0; r < 4; r++) {
                int k = iy - r;
                if (k < 0 || k > 2) continue;
                float wy0 = w0[k], wy1 = w1[k], wy2 = w2[k];
#pragma unroll
                for (int j = 0; j < 4; j++)
                    acc[r][j] += v[j] * wy0 + v[j + 1] * wy1 + v[j + 2] * wy2;
            }
        }
#pragma unroll
        for (int r = 0; r < 4; r++) {
            int yo = y0 + r;
            if (yo >= H) break;
            float* op = opb + (size_t)yo * W;
#pragma unroll
            for (int j = 0; j < 4; j++) {
                int xo = x0 + j;
                if (xo < W)
                    op[xo] = otf32 ? __uint_as_float(f2tf32(acc[r][j])) : acc[r][j];
            }
        }
    }
}

// ---------------- pos dw3 uber: x part (planes 0..2*128) + sp part -----------
__global__ void dw3_pos_uber(const float* __restrict__ x, float* __restrict__ xp,
                             const float* __restrict__ sp, float* __restrict__ spp,
                             const float* __restrict__ w, const float* __restrict__ bias) {
    int py = blockIdx.y;
    const float* in; float* out; int H, W; bool vec;
    int plane;
    if (py < BATCH * DIM) { plane = py; in = x; out = xp; H = W = HX; vec = true; }
    else { plane = py - BATCH * DIM; in = sp; out = spp; H = W = HS; vec = false; }
    int nqx = (W + 3) >> 2, nqy = (H + 3) >> 2;
    int qidx = blockIdx.x * 256 + threadIdx.x;
    if (qidx >= nqx * nqy) return;
    int y0 = (qidx / nqx) << 2, x0 = (qidx % nqx) << 2;
    int c = plane % DIM;
    int HW = H * W;
    dw3_core(in + (size_t)plane * HW, out + (size_t)plane * HW, H, W,
             w + c * 9, 1.0f, bias[c], vec, false, y0, x0);
}

// ---------------- qkv dw3 uber: kv part (512 planes) + q part (256) ----------
__global__ void dw3_qkv_uber(const float* __restrict__ tkv, float* __restrict__ kv,
                             const float* __restrict__ wkvdw,
                             const float* __restrict__ tq, float* __restrict__ q,
                             const float* __restrict__ wqdw) {
    int py = blockIdx.y;
    const float* in; float* out; const float* w; int H, W, cmod; bool vec;
    int plane;
    if (py < BATCH * 2 * DIM) {
        plane = py; in = tkv; out = kv; w = wkvdw; H = W = HX; cmod = 2 * DIM; vec = true;
    } else {
        plane = py - BATCH * 2 * DIM; in = tq; out = q; w = wqdw; H = W = HS; cmod = DIM; vec = false;
    }
    int nqx = (W + 3) >> 2, nqy = (H + 3) >> 2;
    int qidx = blockIdx.x * 256 + threadIdx.x;
    if (qidx >= nqx * nqy) return;
    int y0 = (qidx / nqx) << 2, x0 = (qidx % nqx) << 2;
    int c = plane % cmod;
    int HW = H * W;
    dw3_core(in + (size_t)plane * HW, out + (size_t)plane * HW, H, W,
             w + c * 9, 0.0f, 0.0f, vec, true, y0, x0);
}

// ---------------- conv1 GEMM body (round-6 proven: scalar staging) -----------
__device__ __forceinline__ void gemm128_body(
    const float* __restrict__ Wt, const float* __restrict__ inb,
    float* __restrict__ outb, int O, int P, int p0, int o0,
    uint32_t (*Ws)[16][136], uint32_t (*Xs)[16][136]) {

    int tid = threadIdx.x;
    int lane = tid & 31, warp = tid >> 5;
    int wo = warp >> 2;
    int wp = warp & 3;
    int g = lane >> 2;
    int tq = lane & 3;

    float c[4][4][4];
#pragma unroll
    for (int mi = 0; mi < 4; mi++)
#pragma unroll
        for (int ni = 0; ni < 4; ni++)
#pragma unroll
            for (int r = 0; r < 4; r++) c[mi][ni][r] = 0.0f;

    float wr[8], xr[8];
#pragma unroll
    for (int l = 0; l < 8; l++) {
        int e = tid + l * 256;
        int k = e >> 7, o = e & 127;
        wr[l] = Wt[(size_t)k * O + o0 + o];
        int gp = p0 + o;
        xr[l] = (gp < P) ? inb[(size_t)k * P + gp] : 0.0f;
    }
#pragma unroll
    for (int l = 0; l < 8; l++) {
        int e = tid + l * 256;
        int k = e >> 7, o = e & 127;
        Ws[0][k][o] = f2tf32(wr[l]);
        Xs[0][k][o] = f2tf32(xr[l]);
    }
    __syncthreads();

    for (int kc = 0; kc < 8; kc++) {
        int cur = kc & 1;
        if (kc < 7) {
            int kbase = (kc + 1) * 16;
#pragma unroll
            for (int l = 0; l < 8; l++) {
                int e = tid + l * 256;
                int k = e >> 7, o = e & 127;
                wr[l] = Wt[(size_t)(kbase + k) * O + o0 + o];
                int gp = p0 + o;
                xr[l] = (gp < P) ? inb[(size_t)(kbase + k) * P + gp] : 0.0f;
            }
        }
#pragma unroll
        for (int s = 0; s < 2; s++) {
            int kb = s * 8;
            uint32_t bf[4][2];
#pragma unroll
            for (int ni = 0; ni < 4; ni++) {
                int col = wp * 32 + ni * 8 + g;
                bf[ni][0] = Xs[cur][kb + tq][col];
                bf[ni][1] = Xs[cur][kb + tq + 4][col];
            }
            uint32_t af[4][4];
#pragma unroll
            for (int mi = 0; mi < 4; mi++) {
                int row = wo * 64 + mi * 16 + g;
                af[mi][0] = Ws[cur][kb + tq][row];
                af[mi][1] = Ws[cur][kb + tq][row + 8];
                af[mi][2] = Ws[cur][kb + tq + 4][row];
                af[mi][3] = Ws[cur][kb + tq + 4][row + 8];
            }
#pragma unroll
            for (int mi = 0; mi < 4; mi++)
#pragma unroll
                for (int ni = 0; ni < 4; ni++)
                    MMA_TF32(c[mi][ni][0], c[mi][ni][1], c[mi][ni][2], c[mi][ni][3],
                             af[mi][0], af[mi][1], af[mi][2], af[mi][3],
                             bf[ni][0], bf[ni][1]);
        }
        if (kc < 7) {
            int nb = cur ^ 1;
#pragma unroll
            for (int l = 0; l < 8; l++) {
                int e = tid + l * 256;
                int k = e >> 7, o = e & 127;
                Ws[nb][k][o] = f2tf32(wr[l]);
                Xs[nb][k][o] = f2tf32(xr[l]);
            }
        }
        __syncthreads();
    }

#pragma unroll
    for (int mi = 0; mi < 4; mi++) {
        int row0 = o0 + wo * 64 + mi * 16 + g;
#pragma unroll
        for (int ni = 0; ni < 4; ni++) {
            int col = p0 + wp * 32 + ni * 8 + 2 * tq;
            if (col + 1 < P) {
                float* r0 = outb + (size_t)row0 * P + col;
                float* r1 = outb + (size_t)(row0 + 8) * P + col;
                r0[0] = c[mi][ni][0]; r0[1] = c[mi][ni][1];
                r1[0] = c[mi][ni][2]; r1[1] = c[mi][ni][3];
            } else {
                if (col < P) {
                    outb[(size_t)row0 * P + col] = c[mi][ni][0];
                    outb[(size_t)(row0 + 8) * P + col] = c[mi][ni][2];
                }
            }
        }
    }
}

// big kv GEMM (1924 blocks) + small q GEMM (62 blocks) in one launch
#define NBLK_KV (481*2*BATCH)   // 1924
#define NBLK_Q  (31*BATCH)      // 62
__global__ __launch_bounds__(256, 2)
void conv1_uber(const float* __restrict__ wkvt, const float* __restrict__ xp,
                float* __restrict__ tkv,
                const float* __restrict__ wqt, const float* __restrict__ spp,
                float* __restrict__ tq) {
    __shared__ uint32_t Ws[2][16][136];
    __shared__ uint32_t Xs[2][16][136];
    int bid = blockIdx.x;
    if (bid < NBLK_KV) {
        int p0 = (bid % 481) * 128;
        int rest = bid / 481;
        int o0 = (rest & 1) * 128;
        int bz = rest >> 1;
        gemm128_body(wkvt, xp + (size_t)bz * 128 * PS_X,
                     tkv + (size_t)bz * 256 * PS_X, 256, PS_X, p0, o0, Ws, Xs);
    } else {
        int sid = bid - NBLK_KV;
        int p0 = (sid % 31) * 128;
        int bz = sid / 31;
        gemm128_body(wqt, spp + (size_t)bz * 128 * PS_S,
                     tq + (size_t)bz * 128 * PS_S, 128, PS_S, p0, 0, Ws, Xs);
    }
}

// standalone (final out conv)
__global__ __launch_bounds__(256, 2)
void conv1_single(const float* __restrict__ Wt, const float* __restrict__ in,
                  float* __restrict__ out, int O, int P) {
    __shared__ uint32_t Ws[2][16][136];
    __shared__ uint32_t Xs[2][16][136];
    gemm128_body(Wt, in + (size_t)blockIdx.z * 128 * P,
                 out + (size_t)blockIdx.z * O * P, O, P,
                 blockIdx.x * 128, blockIdx.y * 128, Ws, Xs);
}

// ---------------- windowed attention: cp.async double-buffered K/V -----------
// S computed in log2 domain (log2e folded into w_q); softmax uses ex2 directly.
__global__ __launch_bounds__(128)
void attn_mma_kernel() {
    __shared__ uint32_t qs[64][36];
    __shared__ uint32_t ks[2][32][68];
    __shared__ uint32_t vs[2][32][68];

    int bn = blockIdx.x;
    int h  = blockIdx.y;
    int b = bn / NWIN, n = bn % NWIN;
    int wh = n / 10, ww = n % 10;
    int tid = threadIdx.x, lane = tid & 31, warp = tid >> 5;
    int g = lane >> 2, tq = lane & 3;

    int y0q = 6 * wh, x0q = 6 * ww;
    int y0k = 24 * wh, x0k = 24 * ww;

    uint32_t ks_base = (uint32_t)__cvta_generic_to_shared(&ks[0][0][0]);
    uint32_t vs_base = (uint32_t)__cvta_generic_to_shared(&vs[0][0][0]);

    int u_ch[8], u_j[8], u_isv[8];
    const float* srcp[8];
#pragma unroll
    for (int t = 0; t < 8; t++) {
        int u = tid + (t << 7);
        int isv = u >> 9;
        int uu = u & 511;
        int ch = uu >> 4;
        int rem = uu & 15;
        int row = rem >> 3, kx = (rem & 7) << 2;
        u_ch[t] = ch; u_j[t] = (row << 5) + kx; u_isv[t] = isv;
        srcp[t] = g_kv + (((size_t)(b * 2 * DIM + isv * DIM + h * 32 + ch)) * HX
                          + (y0k + row)) * HX + x0k + kx;
    }

#pragma unroll
    for (int t = 0; t < 8; t++) {
        uint32_t dst = (u_isv[t] ? vs_base : ks_base) + (u_ch[t] * 68 + u_j[t]) * 4;
        cp16(dst, srcp[t]);
    }
    asm volatile("cp.async.commit_group;" ::: "memory");

    const uint32_t* qsrc = (const uint32_t*)g_q;
    for (int e2 = tid; e2 < 1024; e2 += 128) {
        int cch = e2 >> 5;
        int p2 = e2 & 31;
        int i = p2 * 2;
        int dy = i >> 3, dx = i & 7;
        const uint32_t* rowp = qsrc +
            ((size_t)(b * DIM + h * 32 + cch) * HS + y0q + dy) * HS + x0q + dx;
        uint2 v = *(const uint2*)rowp;
        qs[i][cch] = v.x;
        qs[i + 1][cch] = v.y;
    }

    float oacc[4][4];
#pragma unroll
    for (int ni = 0; ni < 4; ni++)
#pragma unroll
        for (int r = 0; r < 4; r++) oacc[ni][r] = 0.0f;
    float mrow0 = -1e30f, mrow1 = -1e30f, lrow0 = 0.0f, lrow1 = 0.0f;

    int m0 = warp * 16;
    int srcl  = (lane & 28) + (tq >> 1);
    int srcl2 = srcl + 2;
    bool odd = (tq & 1);

    for (int i = 0; i < 16; i++) {
        int cur = i & 1;
        if (i < 15) {
            int nb = cur ^ 1;
            int rowoff = (i + 1) * 2 * HX;
#pragma unroll
            for (int t = 0; t < 8; t++) {
                uint32_t dst = (u_isv[t] ? vs_base : ks_base)
                             + ((nb * 32 + u_ch[t]) * 68 + u_j[t]) * 4;
                cp16(dst, srcp[t] + rowoff);
            }
            asm volatile("cp.async.commit_group;" ::: "memory");
            asm volatile("cp.async.wait_group 1;" ::: "memory");
        } else {
            asm volatile("cp.async.wait_group 0;" ::: "memory");
        }
        __syncthreads();

        // ---- S = Q K^T (16 x 64 per warp), log2 domain ----
        float sc[8][4];
#pragma unroll
        for (int ni = 0; ni < 8; ni++)
#pragma unroll
            for (int r = 0; r < 4; r++) sc[ni][r] = 0.0f;

#pragma unroll
        for (int k0 = 0; k0 < 4; k0++) {
            uint32_t a0 = qs[m0 + g][k0 * 8 + tq];
            uint32_t a1 = qs[m0 + g + 8][k0 * 8 + tq];
            uint32_t a2 = qs[m0 + g][k0 * 8 + tq + 4];
            uint32_t a3 = qs[m0 + g + 8][k0 * 8 + tq + 4];
#pragma unroll
            for (int ni = 0; ni < 8; ni++) {
                uint32_t b0 = ks[cur][k0 * 8 + tq][ni * 8 + g];
                uint32_t b1 = ks[cur][k0 * 8 + tq + 4][ni * 8 + g];
                MMA_TF32(sc[ni][0], sc[ni][1], sc[ni][2], sc[ni][3],
                         a0, a1, a2, a3, b0, b1);
            }
        }

        // ---- streaming softmax (base-2) ----
        float mx0 = -1e30f, mx1 = -1e30f;
#pragma unroll
        for (int ni = 0; ni < 8; ni++) {
            mx0 = fmaxf(mx0, fmaxf(sc[ni][0], sc[ni][1]));
            mx1 = fmaxf(mx1, fmaxf(sc[ni][2], sc[ni][3]));
        }
#pragma unroll
        for (int off = 1; off <= 2; off <<= 1) {
            mx0 = fmaxf(mx0, __shfl_xor_sync(0xFFFFFFFFu, mx0, off));
            mx1 = fmaxf(mx1, __shfl_xor_sync(0xFFFFFFFFu, mx1, off));
        }
        float mn0 = fmaxf(mrow0, mx0), mn1 = fmaxf(mrow1, mx1);
        float cor0 = ex2(mrow0 - mn0), cor1 = ex2(mrow1 - mn1);
        mrow0 = mn0; mrow1 = mn1;

        float s0 = 0.0f, s1 = 0.0f;
#pragma unroll
        for (int ni = 0; ni < 8; ni++) {
            sc[ni][0] = ex2(sc[ni][0] - mn0);
            sc[ni][1] = ex2(sc[ni][1] - mn0);
            sc[ni][2] = ex2(sc[ni][2] - mn1);
            sc[ni][3] = ex2(sc[ni][3] - mn1);
            s0 += sc[ni][0] + sc[ni][1];
            s1 += sc[ni][2] + sc[ni][3];
        }
#pragma unroll
        for (int off = 1; off <= 2; off <<= 1) {
            s0 += __shfl_xor_sync(0xFFFFFFFFu, s0, off);
            s1 += __shfl_xor_sync(0xFFFFFFFFu, s1, off);
        }
        lrow0 = lrow0 * cor0 + s0;
        lrow1 = lrow1 * cor1 + s1;
#pragma unroll
        for (int ni = 0; ni < 4; ni++) {
            oacc[ni][0] *= cor0; oacc[ni][1] *= cor0;
            oacc[ni][2] *= cor1; oacc[ni][3] *= cor1;
        }

        // ---- O += P V : A-frags via shfl transpose ----
#pragma unroll
        for (int kk = 0; kk < 8; kk++) {
            uint32_t p0 = f2tf32(sc[kk][0]);
            uint32_t p1 = f2tf32(sc[kk][1]);
            uint32_t p2 = f2tf32(sc[kk][2]);
            uint32_t p3 = f2tf32(sc[kk][3]);
            uint32_t q00 = __shfl_sync(0xFFFFFFFFu, p0, srcl);
            uint32_t q10 = __shfl_sync(0xFFFFFFFFu, p1, srcl);
            uint32_t q20 = __shfl_sync(0xFFFFFFFFu, p2, srcl);
            uint32_t q30 = __shfl_sync(0xFFFFFFFFu, p3, srcl);
            uint32_t q01 = __shfl_sync(0xFFFFFFFFu, p0, srcl2);
            uint32_t q11 = __shfl_sync(0xFFFFFFFFu, p1, srcl2);
            uint32_t q21 = __shfl_sync(0xFFFFFFFFu, p2, srcl2);
            uint32_t q31 = __shfl_sync(0xFFFFFFFFu, p3, srcl2);
            uint32_t a0 = odd ? q10 : q00;
            uint32_t a1 = odd ? q30 : q20;
            uint32_t a2 = odd ? q11 : q01;
            uint32_t a3 = odd ? q31 : q21;
#pragma unroll
            for (int ni = 0; ni < 4; ni++) {
                uint32_t b0 = vs[cur][ni * 8 + g][kk * 8 + tq];
                uint32_t b1 = vs[cur][ni * 8 + g][kk * 8 + tq + 4];
                MMA_TF32(oacc[ni][0], oacc[ni][1], oacc[ni][2], oacc[ni][3],
                         a0, a1, a2, a3, b0, b1);
            }
        }
        __syncthreads();
    }

    float inv0 = 1.0f / lrow0, inv1 = 1.0f / lrow1;
#pragma unroll
    for (int ni = 0; ni < 4; ni++) {
        int col = h * 32 + ni * 8 + 2 * tq;
        size_t base = (size_t)bn * DIM;
        g_win[(base + col) * 64 + m0 + g]         = oacc[ni][0] * inv0;
        g_win[(base + col + 1) * 64 + m0 + g]     = oacc[ni][1] * inv0;
        g_win[(base + col) * 64 + m0 + g + 8]     = oacc[ni][2] * inv1;
        g_win[(base + col + 1) * 64 + m0 + g + 8] = oacc[ni][3] * inv1;
    }
}

// ---------------- reverse (overlap-add with count normalization) -------------
__global__ void reverse_kernel() {
    int idx = blockIdx.x * 256 + threadIdx.x;
    int half = BATCH * DIM * PS_S / 2;
    if (idx >= half + (BATCH * DIM * PS_S & 1)) return;
    int base2 = idx * 2;
    int x = base2 % HS;
    int y = (base2 / HS) % HS;
    int c = (base2 / PS_S) % DIM;
    int b = base2 / (PS_S * DIM);

    float o[2];
#pragma unroll
    for (int t = 0; t < 2; t++) {
        int xx = x + t;
        float s = 0.0f;
        int cnt = 0;
        if (xx < HS) {
            int wlo = max(0, (y - 2) / 6), whi = min(9, y / 6);
            int vlo = max(0, (xx - 2) / 6), vhi = min(9, xx / 6);
            for (int wh = wlo; wh <= whi; wh++) {
                int dy = y - 6 * wh;
                for (int ww = vlo; ww <= vhi; ww++) {
                    int dx = xx - 6 * ww;
                    int n = wh * 10 + ww;
                    s += g_win[((size_t)(b * NWIN + n) * DIM + c) * 64 + dy * 8 + dx];
                }
            }
            cnt = (whi - wlo + 1) * (vhi - vlo + 1);
        }
        o[t] = cnt ? s / (float)cnt : 0.0f;
    }
    float* op = g_acc + (size_t)base2;
    op[0] = o[0];
    if (x + 1 < HS) op[1] = o[1];
}

// ---------------- launch -----------------------------------------------------
extern "C" void kernel_launch(void* const* d_in, const int* in_sizes, int n_in,
                              void* d_out, int out_size) {
    const float* x     = (const float*)d_in[0];
    const float* sp    = (const float*)d_in[1];
    const float* w_pos = (const float*)d_in[2];
    const float* b_pos = (const float*)d_in[3];
    const float* w_q   = (const float*)d_in[4];
    const float* w_qdw = (const float*)d_in[5];
    const float* w_kv  = (const float*)d_in[6];
    const float* w_kvdw= (const float*)d_in[7];
    const float* w_out = (const float*)d_in[8];
    float* out = (float*)d_out;

    float *xp, *spp, *tkv, *kv, *tq, *q, *acc, *wq_t, *wkv_t, *wout_t;
    cudaGetSymbolAddress((void**)&xp,    g_xp);
    cudaGetSymbolAddress((void**)&spp,   g_spp);
    cudaGetSymbolAddress((void**)&tkv,   g_tkv);
    cudaGetSymbolAddress((void**)&kv,    g_kv);
    cudaGetSymbolAddress((void**)&tq,    g_tq);
    cudaGetSymbolAddress((void**)&q,     g_q);
    cudaGetSymbolAddress((void**)&acc,   g_acc);
    cudaGetSymbolAddress((void**)&wq_t,  g_wq_t);
    cudaGetSymbolAddress((void**)&wkv_t, g_wkv_t);
    cudaGetSymbolAddress((void**)&wout_t,g_wout_t);

    // 1/sqrt(32) * log2(e): attention S computed in log2 domain
    const float scale = 0.17677669529663687f * 1.44269504088896340736f;
    transpose_all<<<256, 256>>>(w_q, w_kv, w_out, wq_t, wkv_t, wout_t, scale);

    // pos convs, both tensors, one launch
    dw3_pos_uber<<<dim3(16, BATCH*DIM*2), 256>>>(x, xp, sp, spp, w_pos, b_pos);

    // both 1x1 conv GEMMs (kv big + q small), one launch
    conv1_uber<<<NBLK_KV + NBLK_Q, 256>>>(wkv_t, xp, tkv, wq_t, spp, tq);

    // both depthwise convs (kv + q), one launch, tf32-rounded outputs
    dw3_qkv_uber<<<dim3(16, BATCH*2*DIM + BATCH*DIM), 256>>>(
        tkv, kv, w_kvdw, tq, q, w_qdw);

    attn_mma_kernel<<<dim3(BATCH*NWIN, 4), 128>>>();

    reverse_kernel<<<(BATCH*DIM*PS_S/2 + 255)/256, 256>>>();

    conv1_single<<<dim3((PS_S + 127)/128, 1, BATCH), 256>>>(wout_t, acc, out, DIM, PS_S);
}

// round 10
// speedup vs baseline: 1.3760x; 1.1789x over previous
#include <cuda_runtime.h>
#include <cuda_fp16.h>
#include <cstdint>

#define BATCH 2
#define DIM   128
#define HS    62
#define HX    248
#define PS_S  (HS*HS)   // 3844
#define PS_X  (HX*HX)   // 61504
#define NWIN  100       // 10x10 windows

// ---------------- scratch ----------------------------------------------------
__device__ float    g_xp  [BATCH*DIM*PS_X];
__device__ float    g_spp [BATCH*DIM*PS_S];
__device__ float    g_tkv [BATCH*2*DIM*PS_X];   // conv1 out, fp32
__device__ float    g_tq  [BATCH*DIM*PS_S];     // conv1 out, fp32
__device__ uint32_t g_ki  [BATCH*64*PS_X];      // K fp16, ch-pair interleaved
__device__ __half   g_v   [BATCH*DIM*PS_X];     // V fp16, plain planes
__device__ uint32_t g_qi  [BATCH*64*PS_S];      // Q fp16, ch-pair interleaved
__device__ float    g_win [BATCH*NWIN*DIM*64];
__device__ float    g_acc [BATCH*DIM*PS_S];
__device__ float    g_wq_t  [DIM*DIM];
__device__ float    g_wkv_t [DIM*2*DIM];
__device__ float    g_wout_t[DIM*DIM];

__device__ __forceinline__ uint32_t f2tf32(float f) {
    uint32_t u;
    asm("cvt.rna.tf32.f32 %0, %1;" : "=r"(u) : "f"(f));
    return u;
}
__device__ __forceinline__ float ex2(float x) {
    float y;
    asm("ex2.approx.f32 %0, %1;" : "=f"(y) : "f"(x));
    return y;
}
__device__ __forceinline__ uint32_t h2pack(float lo, float hi) {
    __half2 hh = __floats2half2_rn(lo, hi);   // x = lo, y = hi
    return *reinterpret_cast<uint32_t*>(&hh);
}

#define MMA_TF32(C0,C1,C2,C3,A0,A1,A2,A3,B0,B1)                               \
    asm volatile(                                                             \
        "mma.sync.aligned.m16n8k8.row.col.f32.tf32.tf32.f32 "                 \
        "{%0,%1,%2,%3}, {%4,%5,%6,%7}, {%8,%9}, {%0,%1,%2,%3};"               \
        : "+f"(C0), "+f"(C1), "+f"(C2), "+f"(C3)                              \
        : "r"(A0), "r"(A1), "r"(A2), "r"(A3), "r"(B0), "r"(B1))

#define MMA_F16(C0,C1,C2,C3,A0,A1,A2,A3,B0,B1)                                \
    asm volatile(                                                             \
        "mma.sync.aligned.m16n8k16.row.col.f32.f16.f16.f32 "                  \
        "{%0,%1,%2,%3}, {%4,%5,%6,%7}, {%8,%9}, {%0,%1,%2,%3};"               \
        : "+f"(C0), "+f"(C1), "+f"(C2), "+f"(C3)                              \
        : "r"(A0), "r"(A1), "r"(A2), "r"(A3), "r"(B0), "r"(B1))

__device__ __forceinline__ void cp16(uint32_t dst, const void* src) {
    asm volatile("cp.async.cg.shared.global [%0], [%1], 16;" :: "r"(dst), "l"(src));
}

// ---------------- all weight transposes in one kernel ------------------------
__global__ void transpose_all(const float* __restrict__ wq,
                              const float* __restrict__ wkv,
                              const float* __restrict__ wout,
                              float* __restrict__ wqt,
                              float* __restrict__ wkvt,
                              float* __restrict__ woutt, float scale) {
    int idx = blockIdx.x * 256 + threadIdx.x;
    if (idx < 16384) {
        int o = idx >> 7, c = idx & 127;
        wqt[c * 128 + o] = wq[idx] * scale;
    } else if (idx < 49152) {
        int i = idx - 16384;
        int o = i >> 7, c = i & 127;
        wkvt[c * 256 + o] = wkv[i];
    } else if (idx < 65536) {
        int i = idx - 49152;
        int o = i >> 7, c = i & 127;
        woutt[c * 128 + o] = wout[i];
    }
}

// ---------------- depthwise 3x3 compute (4x4 px/thread), no stores -----------
__device__ __forceinline__ bool dw3_compute(const float* __restrict__ ip,
                                            int H, int W,
                                            const float* __restrict__ wc,
                                            float centerAdd, float binit,
                                            bool vec, int y0, int x0,
                                            float acc[4][4]) {
    float w0[3] = {wc[0], wc[3], wc[6]};
    float w1[3] = {wc[1], wc[4] + centerAdd, wc[7]};
    float w2[3] = {wc[2], wc[5], wc[8]};
#pragma unroll
    for (int r = 0; r < 4; r++)
#pragma unroll
        for (int j = 0; j < 4; j++) acc[r][j] = binit;

    bool xint = (x0 >= 4) && (x0 + 8 <= W);
    bool yint = (y0 >= 1) && (y0 + 5 <= H);
    bool fast = vec && xint && yint;

    if (fast) {
#pragma unroll
        for (int iy = 0; iy < 6; iy++) {
            const float* rp = ip + (size_t)(y0 + iy - 1) * W;
            float4 mid = *(const float4*)(rp + x0);
            float v0 = rp[x0 - 1], v5 = rp[x0 + 4];
            float v[6] = {v0, mid.x, mid.y, mid.z, mid.w, v5};
#pragma unroll
            for (int r = 0; r < 4; r++) {
                int k = iy - r;
                if (k < 0 || k > 2) continue;
                float wy0 = w0[k], wy1 = w1[k], wy2 = w2[k];
#pragma unroll
                for (int j = 0; j < 4; j++)
                    acc[r][j] += v[j] * wy0 + v[j + 1] * wy1 + v[j + 2] * wy2;
            }
        }
    } else {
#pragma unroll
        for (int iy = 0; iy < 6; iy++) {
            int yy = y0 + iy - 1;
            if ((unsigned)yy >= (unsigned)H) continue;
            const float* rp = ip + (size_t)yy * W;
            float v[6];
#pragma unroll
            for (int i = 0; i < 6; i++) {
                int xx = x0 - 1 + i;
                v[i] = ((unsigned)xx < (unsigned)W) ? rp[xx] : 0.0f;
            }
#pragma unroll
            for (int r = 0; r < 4; r++) {
                int k = iy - r;
                if (k < 0 || k > 2) continue;
                float wy0 = w0[k], wy1 = w1[k], wy2 = w2[k];
#pragma unroll
                for (int j = 0; j < 4; j++)
                    acc[r][j] += v[j] * wy0 + v[j + 1] * wy1 + v[j + 2] * wy2;
            }
        }
    }
    return fast;
}

// ---------------- pos dw3 uber (fp32 out, unchanged) -------------------------
__global__ void dw3_pos_uber(const float* __restrict__ x, float* __restrict__ xp,
                             const float* __restrict__ sp, float* __restrict__ spp,
                             const float* __restrict__ w, const float* __restrict__ bias) {
    int py = blockIdx.y;
    const float* in; float* out; int H, W; bool vec;
    int plane;
    if (py < BATCH * DIM) { plane = py; in = x; out = xp; H = W = HX; vec = true; }
    else { plane = py - BATCH * DIM; in = sp; out = spp; H = W = HS; vec = false; }
    int nqx = (W + 3) >> 2, nqy = (H + 3) >> 2;
    int qidx = blockIdx.x * 256 + threadIdx.x;
    if (qidx >= nqx * nqy) return;
    int y0 = (qidx / nqx) << 2, x0 = (qidx % nqx) << 2;
    int c = plane % DIM;
    int HW = H * W;
    float acc[4][4];
    bool fast = dw3_compute(in + (size_t)plane * HW, H, W, w + c * 9,
                            1.0f, bias[c], vec, y0, x0, acc);
    float* opb = out + (size_t)plane * HW;
    if (fast) {
#pragma unroll
        for (int r = 0; r < 4; r++)
            *(float4*)(opb + (size_t)(y0 + r) * W + x0) =
                make_float4(acc[r][0], acc[r][1], acc[r][2], acc[r][3]);
    } else {
#pragma unroll
        for (int r = 0; r < 4; r++) {
            int yo = y0 + r;
            if (yo >= H) break;
#pragma unroll
            for (int j = 0; j < 4; j++) {
                int xo = x0 + j;
                if (xo < W) opb[(size_t)yo * W + xo] = acc[r][j];
            }
        }
    }
}

// ---------------- qkv dw3 uber: fp16 outputs in mma-friendly layouts ---------
// y-plane decode: [0, B*64)           : K channel-pairs -> g_ki interleaved
//                 [B*64, B*64+B*128)  : V single channels -> g_v plain
//                 [B*64+B*128, +B*64) : Q channel-pairs -> g_qi interleaved
__global__ void dw3_qkv_uber(const float* __restrict__ wkvdw,
                             const float* __restrict__ wqdw) {
    int py = blockIdx.y;
    int qidx = blockIdx.x * 256 + threadIdx.x;

    if (py < BATCH * 64) {                       // ---- K pairs ----
        if (qidx >= 62 * 62) return;
        int b = py >> 6, cp = py & 63;
        int y0 = (qidx / 62) << 2, x0 = (qidx % 62) << 2;
        const float* in0 = g_tkv + ((size_t)(b * 256 + 2 * cp)) * PS_X;
        float a0[4][4], a1[4][4];
        bool fast = dw3_compute(in0, HX, HX, wkvdw + (2 * cp) * 9,
                                0.0f, 0.0f, true, y0, x0, a0);
        dw3_compute(in0 + PS_X, HX, HX, wkvdw + (2 * cp + 1) * 9,
                    0.0f, 0.0f, true, y0, x0, a1);
        uint32_t* op = g_ki + ((size_t)(b * 64 + cp)) * PS_X;
        if (fast) {
#pragma unroll
            for (int r = 0; r < 4; r++) {
                uint4 u = {h2pack(a0[r][0], a1[r][0]), h2pack(a0[r][1], a1[r][1]),
                           h2pack(a0[r][2], a1[r][2]), h2pack(a0[r][3], a1[r][3])};
                *(uint4*)(op + (size_t)(y0 + r) * HX + x0) = u;
            }
        } else {
#pragma unroll
            for (int r = 0; r < 4; r++) {
                int yo = y0 + r;
                if (yo >= HX) break;
#pragma unroll
                for (int j = 0; j < 4; j++) {
                    int xo = x0 + j;
                    if (xo < HX)
                        op[(size_t)yo * HX + xo] = h2pack(a0[r][j], a1[r][j]);
                }
            }
        }
    } else if (py < BATCH * 64 + BATCH * 128) {  // ---- V plain ----
        if (qidx >= 62 * 62) return;
        int p = py - BATCH * 64;
        int b = p >> 7, c = p & 127;
        int y0 = (qidx / 62) << 2, x0 = (qidx % 62) << 2;
        const float* in = g_tkv + ((size_t)(b * 256 + 128 + c)) * PS_X;
        float a[4][4];
        bool fast = dw3_compute(in, HX, HX, wkvdw + (128 + c) * 9,
                                0.0f, 0.0f, true, y0, x0, a);
        __half* op = g_v + ((size_t)(b * 128 + c)) * PS_X;
        if (fast) {
#pragma unroll
            for (int r = 0; r < 4; r++) {
                __half2 lo = __floats2half2_rn(a[r][0], a[r][1]);
                __half2 hi = __floats2half2_rn(a[r][2], a[r][3]);
                uint2 u = {*reinterpret_cast<uint32_t*>(&lo),
                           *reinterpret_cast<uint32_t*>(&hi)};
                *(uint2*)(op + (size_t)(y0 + r) * HX + x0) = u;
            }
        } else {
#pragma unroll
            for (int r = 0; r < 4; r++) {
                int yo = y0 + r;
                if (yo >= HX) break;
#pragma unroll
                for (int j = 0; j < 4; j++) {
                    int xo = x0 + j;
                    if (xo < HX) op[(size_t)yo * HX + xo] = __float2half_rn(a[r][j]);
                }
            }
        }
    } else {                                     // ---- Q pairs ----
        if (qidx >= 16 * 16) return;
        int p = py - BATCH * 64 - BATCH * 128;
        int b = p >> 6, cp = p & 63;
        int y0 = (qidx / 16) << 2, x0 = (qidx % 16) << 2;
        const float* in0 = g_tq + ((size_t)(b * 128 + 2 * cp)) * PS_S;
        float a0[4][4], a1[4][4];
        dw3_compute(in0, HS, HS, wqdw + (2 * cp) * 9, 0.0f, 0.0f, false, y0, x0, a0);
        dw3_compute(in0 + PS_S, HS, HS, wqdw + (2 * cp + 1) * 9, 0.0f, 0.0f, false, y0, x0, a1);
        uint32_t* op = g_qi + ((size_t)(b * 64 + cp)) * PS_S;
#pragma unroll
        for (int r = 0; r < 4; r++) {
            int yo = y0 + r;
            if (yo >= HS) break;
#pragma unroll
            for (int j = 0; j < 4; j++) {
                int xo = x0 + j;
                if (xo < HS) op[(size_t)yo * HS + xo] = h2pack(a0[r][j], a1[r][j]);
            }
        }
    }
}

// ---------------- conv1 GEMM body (round-6 proven: scalar staging) -----------
__device__ __forceinline__ void gemm128_body(
    const float* __restrict__ Wt, const float* __restrict__ inb,
    float* __restrict__ outb, int O, int P, int p0, int o0,
    uint32_t (*Ws)[16][136], uint32_t (*Xs)[16][136]) {

    int tid = threadIdx.x;
    int lane = tid & 31, warp = tid >> 5;
    int wo = warp >> 2;
    int wp = warp & 3;
    int g = lane >> 2;
    int tq = lane & 3;

    float c[4][4][4];
#pragma unroll
    for (int mi = 0; mi < 4; mi++)
#pragma unroll
        for (int ni = 0; ni < 4; ni++)
#pragma unroll
            for (int r = 0; r < 4; r++) c[mi][ni][r] = 0.0f;

    float wr[8], xr[8];
#pragma unroll
    for (int l = 0; l < 8; l++) {
        int e = tid + l * 256;
        int k = e >> 7, o = e & 127;
        wr[l] = Wt[(size_t)k * O + o0 + o];
        int gp = p0 + o;
        xr[l] = (gp < P) ? inb[(size_t)k * P + gp] : 0.0f;
    }
#pragma unroll
    for (int l = 0; l < 8; l++) {
        int e = tid + l * 256;
        int k = e >> 7, o = e & 127;
        Ws[0][k][o] = f2tf32(wr[l]);
        Xs[0][k][o] = f2tf32(xr[l]);
    }
    __syncthreads();

    for (int kc = 0; kc < 8; kc++) {
        int cur = kc & 1;
        if (kc < 7) {
            int kbase = (kc + 1) * 16;
#pragma unroll
            for (int l = 0; l < 8; l++) {
                int e = tid + l * 256;
                int k = e >> 7, o = e & 127;
                wr[l] = Wt[(size_t)(kbase + k) * O + o0 + o];
                int gp = p0 + o;
                xr[l] = (gp < P) ? inb[(size_t)(kbase + k) * P + gp] : 0.0f;
            }
        }
#pragma unroll
        for (int s = 0; s < 2; s++) {
            int kb = s * 8;
            uint32_t bf[4][2];
#pragma unroll
            for (int ni = 0; ni < 4; ni++) {
                int col = wp * 32 + ni * 8 + g;
                bf[ni][0] = Xs[cur][kb + tq][col];
                bf[ni][1] = Xs[cur][kb + tq + 4][col];
            }
            uint32_t af[4][4];
#pragma unroll
            for (int mi = 0; mi < 4; mi++) {
                int row = wo * 64 + mi * 16 + g;
                af[mi][0] = Ws[cur][kb + tq][row];
                af[mi][1] = Ws[cur][kb + tq][row + 8];
                af[mi][2] = Ws[cur][kb + tq + 4][row];
                af[mi][3] = Ws[cur][kb + tq + 4][row + 8];
            }
#pragma unroll
            for (int mi = 0; mi < 4; mi++)
#pragma unroll
                for (int ni = 0; ni < 4; ni++)
                    MMA_TF32(c[mi][ni][0], c[mi][ni][1], c[mi][ni][2], c[mi][ni][3],
                             af[mi][0], af[mi][1], af[mi][2], af[mi][3],
                             bf[ni][0], bf[ni][1]);
        }
        if (kc < 7) {
            int nb = cur ^ 1;
#pragma unroll
            for (int l = 0; l < 8; l++) {
                int e = tid + l * 256;
                int k = e >> 7, o = e & 127;
                Ws[nb][k][o] = f2tf32(wr[l]);
                Xs[nb][k][o] = f2tf32(xr[l]);
            }
        }
        __syncthreads();
    }

#pragma unroll
    for (int mi = 0; mi < 4; mi++) {
        int row0 = o0 + wo * 64 + mi * 16 + g;
#pragma unroll
        for (int ni = 0; ni < 4; ni++) {
            int col = p0 + wp * 32 + ni * 8 + 2 * tq;
            if (col + 1 < P) {
                float* r0 = outb + (size_t)row0 * P + col;
                float* r1 = outb + (size_t)(row0 + 8) * P + col;
                r0[0] = c[mi][ni][0]; r0[1] = c[mi][ni][1];
                r1[0] = c[mi][ni][2]; r1[1] = c[mi][ni][3];
            } else {
                if (col < P) {
                    outb[(size_t)row0 * P + col] = c[mi][ni][0];
                    outb[(size_t)(row0 + 8) * P + col] = c[mi][ni][2];
                }
            }
        }
    }
}

#define NBLK_KV (481*2*BATCH)   // 1924
#define NBLK_Q  (31*BATCH)      // 62
__global__ __launch_bounds__(256, 2)
void conv1_uber(const float* __restrict__ wkvt, const float* __restrict__ xp,
                float* __restrict__ tkv,
                const float* __restrict__ wqt, const float* __restrict__ spp,
                float* __restrict__ tq) {
    __shared__ uint32_t Ws[2][16][136];
    __shared__ uint32_t Xs[2][16][136];
    int bid = blockIdx.x;
    if (bid < NBLK_KV) {
        int p0 = (bid % 481) * 128;
        int rest = bid / 481;
        int o0 = (rest & 1) * 128;
        int bz = rest >> 1;
        gemm128_body(wkvt, xp + (size_t)bz * 128 * PS_X,
                     tkv + (size_t)bz * 256 * PS_X, 256, PS_X, p0, o0, Ws, Xs);
    } else {
        int sid = bid - NBLK_KV;
        int p0 = (sid % 31) * 128;
        int bz = sid / 31;
        gemm128_body(wqt, spp + (size_t)bz * 128 * PS_S,
                     tq + (size_t)bz * 128 * PS_S, 128, PS_S, p0, 0, Ws, Xs);
    }
}

__global__ __launch_bounds__(256, 2)
void conv1_single(const float* __restrict__ Wt, const float* __restrict__ in,
                  float* __restrict__ out, int O, int P) {
    __shared__ uint32_t Ws[2][16][136];
    __shared__ uint32_t Xs[2][16][136];
    gemm128_body(Wt, in + (size_t)blockIdx.z * 128 * P,
                 out + (size_t)blockIdx.z * O * P, O, P,
                 blockIdx.x * 128, blockIdx.y * 128, Ws, Xs);
}

// ---------------- windowed attention: fp16 mma, zero-shuffle PV --------------
__global__ __launch_bounds__(128)
void attn_mma_kernel() {
    __shared__ uint32_t qs[16][72];       // [chpair][qpos]
    __shared__ uint32_t ks[2][16][72];    // [buf][chpair][kvpos]
    __shared__ uint32_t vs[2][32][36];    // [buf][ch][pospair]

    int bn = blockIdx.x;
    int h  = blockIdx.y;
    int b = bn / NWIN, n = bn % NWIN;
    int wh = n / 10, ww = n % 10;
    int tid = threadIdx.x, lane = tid & 31, warp = tid >> 5;
    int g = lane >> 2, tq = lane & 3;

    int y0q = 6 * wh, x0q = 6 * ww;
    int y0k = 24 * wh, x0k = 24 * ww;

    const int KSB = 16 * 72;   // uint32 per ks buffer
    const int VSB = 32 * 36;

    // cp.async descriptors: 2 ks + 2 vs segments of 16B per thread per chunk
    const uint32_t* ksrc[2]; uint32_t kdst[2];
#pragma unroll
    for (int t = 0; t < 2; t++) {
        int u = tid + t * 128;
        int cp = u >> 4, rem = u & 15, row = rem >> 3, xq = rem & 7;
        ksrc[t] = g_ki + ((size_t)(b * 64 + h * 16 + cp)) * PS_X
                + (y0k + row) * HX + x0k + xq * 4;
        kdst[t] = (uint32_t)__cvta_generic_to_shared(&ks[0][cp][row * 32 + xq * 4]);
    }
    const uint32_t* vsrc[2]; uint32_t vdst[2];
    const uint32_t* gv32 = (const uint32_t*)g_v;
#pragma unroll
    for (int t = 0; t < 2; t++) {
        int u = tid + t * 128;
        int ch = u >> 3, rem = u & 7, row = rem >> 2, xq = rem & 3;
        vsrc[t] = gv32 + (((size_t)(b * 128 + h * 32 + ch)) * PS_X
                          + (y0k + row) * HX + x0k) / 2 + xq * 4;
        vdst[t] = (uint32_t)__cvta_generic_to_shared(&vs[0][ch][row * 16 + xq * 4]);
    }

    // issue chunk 0 into buf 0
#pragma unroll
    for (int t = 0; t < 2; t++) cp16(kdst[t], ksrc[t]);
#pragma unroll
    for (int t = 0; t < 2; t++) cp16(vdst[t], vsrc[t]);
    asm volatile("cp.async.commit_group;" ::: "memory");

    // stage q: [chpair][qpos], 8B loads
    const uint32_t* qsrc = g_qi + ((size_t)(b * 64 + h * 16)) * PS_S;
    for (int e = tid; e < 512; e += 128) {
        int cp = e >> 5, ip = e & 31;
        int i = ip * 2;
        int dy = i >> 3, dx = i & 7;
        uint2 v = *(const uint2*)(qsrc + (size_t)cp * PS_S + (y0q + dy) * HS + x0q + dx);
        qs[cp][i] = v.x;
        qs[cp][i + 1] = v.y;
    }

    float oacc[4][4];
#pragma unroll
    for (int ni = 0; ni < 4; ni++)
#pragma unroll
        for (int r = 0; r < 4; r++) oacc[ni][r] = 0.0f;
    float mrow0 = -1e30f, mrow1 = -1e30f, lrow0 = 0.0f, lrow1 = 0.0f;

    int m0 = warp * 16;

    for (int i = 0; i < 16; i++) {
        int cur = i & 1;
        if (i < 15) {
            int nb = cur ^ 1;
            int koff = (i + 1) * 2 * HX;   // uint32 units (K interleaved)
            int voff = (i + 1) * HX;       // uint32 units (V halves/2)
#pragma unroll
            for (int t = 0; t < 2; t++) cp16(kdst[t] + nb * KSB * 4, ksrc[t] + koff);
#pragma unroll
            for (int t = 0; t < 2; t++) cp16(vdst[t] + nb * VSB * 4, vsrc[t] + voff);
            asm volatile("cp.async.commit_group;" ::: "memory");
            asm volatile("cp.async.wait_group 1;" ::: "memory");
        } else {
            asm volatile("cp.async.wait_group 0;" ::: "memory");
        }
        __syncthreads();

        // ---- S = Q K^T (16 x 64 per warp), fp16 mma, log2 domain ----
        float sc[8][4];
#pragma unroll
        for (int ni = 0; ni < 8; ni++)
#pragma unroll
            for (int r = 0; r < 4; r++) sc[ni][r] = 0.0f;

#pragma unroll
        for (int k0 = 0; k0 < 2; k0++) {
            uint32_t a0 = qs[k0 * 8 + tq][m0 + g];
            uint32_t a1 = qs[k0 * 8 + tq][m0 + g + 8];
            uint32_t a2 = qs[k0 * 8 + tq + 4][m0 + g];
            uint32_t a3 = qs[k0 * 8 + tq + 4][m0 + g + 8];
#pragma unroll
            for (int ni = 0; ni < 8; ni++) {
                uint32_t b0 = ks[cur][k0 * 8 + tq][ni * 8 + g];
                uint32_t b1 = ks[cur][k0 * 8 + tq + 4][ni * 8 + g];
                MMA_F16(sc[ni][0], sc[ni][1], sc[ni][2], sc[ni][3],
                        a0, a1, a2, a3, b0, b1);
            }
        }

        // ---- streaming softmax (base-2) ----
        float mx0 = -1e30f, mx1 = -1e30f;
#pragma unroll
        for (int ni = 0; ni < 8; ni++) {
            mx0 = fmaxf(mx0, fmaxf(sc[ni][0], sc[ni][1]));
            mx1 = fmaxf(mx1, fmaxf(sc[ni][2], sc[ni][3]));
        }
#pragma unroll
        for (int off = 1; off <= 2; off <<= 1) {
            mx0 = fmaxf(mx0, __shfl_xor_sync(0xFFFFFFFFu, mx0, off));
            mx1 = fmaxf(mx1, __shfl_xor_sync(0xFFFFFFFFu, mx1, off));
        }
        float mn0 = fmaxf(mrow0, mx0), mn1 = fmaxf(mrow1, mx1);
        float cor0 = ex2(mrow0 - mn0), cor1 = ex2(mrow1 - mn1);
        mrow0 = mn0; mrow1 = mn1;

        float s0 = 0.0f, s1 = 0.0f;
#pragma unroll
        for (int ni = 0; ni < 8; ni++) {
            sc[ni][0] = ex2(sc[ni][0] - mn0);
            sc[ni][1] = ex2(sc[ni][1] - mn0);
            sc[ni][2] = ex2(sc[ni][2] - mn1);
            sc[ni][3] = ex2(sc[ni][3] - mn1);
            s0 += sc[ni][0] + sc[ni][1];
            s1 += sc[ni][2] + sc[ni][3];
        }
#pragma unroll
        for (int off = 1; off <= 2; off <<= 1) {
            s0 += __shfl_xor_sync(0xFFFFFFFFu, s0, off);
            s1 += __shfl_xor_sync(0xFFFFFFFFu, s1, off);
        }
        lrow0 = lrow0 * cor0 + s0;
        lrow1 = lrow1 * cor1 + s1;
#pragma unroll
        for (int ni = 0; ni < 4; ni++) {
            oacc[ni][0] *= cor0; oacc[ni][1] *= cor0;
            oacc[ni][2] *= cor1; oacc[ni][3] *= cor1;
        }

        // ---- O += P V : A-frags are repacked C-frags (NO shuffles) ----
#pragma unroll
        for (int kk = 0; kk < 4; kk++) {
            uint32_t a0 = h2pack(sc[2 * kk][0],     sc[2 * kk][1]);
            uint32_t a1 = h2pack(sc[2 * kk][2],     sc[2 * kk][3]);
            uint32_t a2 = h2pack(sc[2 * kk + 1][0], sc[2 * kk + 1][1]);
            uint32_t a3 = h2pack(sc[2 * kk + 1][2], sc[2 * kk + 1][3]);
#pragma unroll
            for (int ni = 0; ni < 4; ni++) {
                uint32_t b0 = vs[cur][ni * 8 + g][kk * 8 + tq];
                uint32_t b1 = vs[cur][ni * 8 + g][kk * 8 + tq + 4];
                MMA_F16(oacc[ni][0], oacc[ni][1], oacc[ni][2], oacc[ni][3],
                        a0, a1, a2, a3, b0, b1);
            }
        }
        __syncthreads();
    }

    float inv0 = 1.0f / lrow0, inv1 = 1.0f / lrow1;
#pragma unroll
    for (int ni = 0; ni < 4; ni++) {
        int col = h * 32 + ni * 8 + 2 * tq;
        size_t base = (size_t)bn * DIM;
        g_win[(base + col) * 64 + m0 + g]         = oacc[ni][0] * inv0;
        g_win[(base + col + 1) * 64 + m0 + g]     = oacc[ni][1] * inv0;
        g_win[(base + col) * 64 + m0 + g + 8]     = oacc[ni][2] * inv1;
        g_win[(base + col + 1) * 64 + m0 + g + 8] = oacc[ni][3] * inv1;
    }
}

// ---------------- reverse (overlap-add with count normalization) -------------
__global__ void reverse_kernel() {
    int idx = blockIdx.x * 256 + threadIdx.x;
    int half = BATCH * DIM * PS_S / 2;
    if (idx >= half + (BATCH * DIM * PS_S & 1)) return;
    int base2 = idx * 2;
    int x = base2 % HS;
    int y = (base2 / HS) % HS;
    int c = (base2 / PS_S) % DIM;
    int b = base2 / (PS_S * DIM);

    float o[2];
#pragma unroll
    for (int t = 0; t < 2; t++) {
        int xx = x + t;
        float s = 0.0f;
        int cnt = 0;
        if (xx < HS) {
            int wlo = max(0, (y - 2) / 6), whi = min(9, y / 6);
            int vlo = max(0, (xx - 2) / 6), vhi = min(9, xx / 6);
            for (int wh = wlo; wh <= whi; wh++) {
                int dy = y - 6 * wh;
                for (int ww = vlo; ww <= vhi; ww++) {
                    int dx = xx - 6 * ww;
                    int n = wh * 10 + ww;
                    s += g_win[((size_t)(b * NWIN + n) * DIM + c) * 64 + dy * 8 + dx];
                }
            }
            cnt = (whi - wlo + 1) * (vhi - vlo + 1);
        }
        o[t] = cnt ? s / (float)cnt : 0.0f;
    }
    float* op = g_acc + (size_t)base2;
    op[0] = o[0];
    if (x + 1 < HS) op[1] = o[1];
}

// ---------------- launch -----------------------------------------------------
extern "C" void kernel_launch(void* const* d_in, const int* in_sizes, int n_in,
                              void* d_out, int out_size) {
    const float* x     = (const float*)d_in[0];
    const float* sp    = (const float*)d_in[1];
    const float* w_pos = (const float*)d_in[2];
    const float* b_pos = (const float*)d_in[3];
    const float* w_q   = (const float*)d_in[4];
    const float* w_qdw = (const float*)d_in[5];
    const float* w_kv  = (const float*)d_in[6];
    const float* w_kvdw= (const float*)d_in[7];
    const float* w_out = (const float*)d_in[8];
    float* out = (float*)d_out;

    float *xp, *spp, *tkv, *tq, *acc, *wq_t, *wkv_t, *wout_t;
    cudaGetSymbolAddress((void**)&xp,    g_xp);
    cudaGetSymbolAddress((void**)&spp,   g_spp);
    cudaGetSymbolAddress((void**)&tkv,   g_tkv);
    cudaGetSymbolAddress((void**)&tq,    g_tq);
    cudaGetSymbolAddress((void**)&acc,   g_acc);
    cudaGetSymbolAddress((void**)&wq_t,  g_wq_t);
    cudaGetSymbolAddress((void**)&wkv_t, g_wkv_t);
    cudaGetSymbolAddress((void**)&wout_t,g_wout_t);

    // 1/sqrt(32) * log2(e): attention S computed in log2 domain
    const float scale = 0.17677669529663687f * 1.44269504088896340736f;
    transpose_all<<<256, 256>>>(w_q, w_kv, w_out, wq_t, wkv_t, wout_t, scale);

    dw3_pos_uber<<<dim3(16, BATCH*DIM*2), 256>>>(x, xp, sp, spp, w_pos, b_pos);

    conv1_uber<<<NBLK_KV + NBLK_Q, 256>>>(wkv_t, xp, tkv, wq_t, spp, tq);

    // fp16 depthwise: K pairs + V plain + Q pairs, one launch
    dw3_qkv_uber<<<dim3(16, BATCH*64 + BATCH*128 + BATCH*64), 256>>>(w_kvdw, w_qdw);

    attn_mma_kernel<<<dim3(BATCH*NWIN, 4), 128>>>();

    reverse_kernel<<<(BATCH*DIM*PS_S/2 + 255)/256, 256>>>();

    conv1_single<<<dim3((PS_S + 127)/128, 1, BATCH), 256>>>(wout_t, acc, out, DIM, PS_S);
}

// round 11
// speedup vs baseline: 1.5545x; 1.1297x over previous
#include <cuda_runtime.h>
#include <cuda_fp16.h>
#include <cstdint>

#define BATCH 2
#define DIM   128
#define HS    62
#define HX    248
#define PS_S  (HS*HS)   // 3844
#define PS_X  (HX*HX)   // 61504
#define NWIN  100       // 10x10 windows

// ---------------- scratch ----------------------------------------------------
__device__ __half   g_xp  [BATCH*DIM*PS_X];     // x + pos-conv (fp16)
__device__ __half   g_spp [BATCH*DIM*PS_S];     // sp + pos-conv (fp16)
__device__ __half   g_tkv [BATCH*2*DIM*PS_X];   // conv1 kv out (fp16)
__device__ __half   g_tq  [BATCH*DIM*PS_S];     // conv1 q out (fp16)
__device__ uint32_t g_ki  [BATCH*64*PS_X];      // K fp16, ch-pair interleaved
__device__ __half   g_v   [BATCH*DIM*PS_X];     // V fp16, plain planes
__device__ uint32_t g_qi  [BATCH*64*PS_S];      // Q fp16, ch-pair interleaved
__device__ float    g_win [BATCH*NWIN*DIM*64];
__device__ float    g_acc [BATCH*DIM*PS_S];
__device__ float    g_wq_t  [DIM*DIM];
__device__ float    g_wkv_t [DIM*2*DIM];
__device__ float    g_wout_t[DIM*DIM];

__device__ __forceinline__ uint32_t f2tf32(float f) {
    uint32_t u;
    asm("cvt.rna.tf32.f32 %0, %1;" : "=r"(u) : "f"(f));
    return u;
}
__device__ __forceinline__ float ex2(float x) {
    float y;
    asm("ex2.approx.f32 %0, %1;" : "=f"(y) : "f"(x));
    return y;
}
__device__ __forceinline__ uint32_t h2pack(float lo, float hi) {
    __half2 hh = __floats2half2_rn(lo, hi);
    return *reinterpret_cast<uint32_t*>(&hh);
}

#define MMA_TF32(C0,C1,C2,C3,A0,A1,A2,A3,B0,B1)                               \
    asm volatile(                                                             \
        "mma.sync.aligned.m16n8k8.row.col.f32.tf32.tf32.f32 "                 \
        "{%0,%1,%2,%3}, {%4,%5,%6,%7}, {%8,%9}, {%0,%1,%2,%3};"               \
        : "+f"(C0), "+f"(C1), "+f"(C2), "+f"(C3)                              \
        : "r"(A0), "r"(A1), "r"(A2), "r"(A3), "r"(B0), "r"(B1))

#define MMA_F16(C0,C1,C2,C3,A0,A1,A2,A3,B0,B1)                                \
    asm volatile(                                                             \
        "mma.sync.aligned.m16n8k16.row.col.f32.f16.f16.f32 "                  \
        "{%0,%1,%2,%3}, {%4,%5,%6,%7}, {%8,%9}, {%0,%1,%2,%3};"               \
        : "+f"(C0), "+f"(C1), "+f"(C2), "+f"(C3)                              \
        : "r"(A0), "r"(A1), "r"(A2), "r"(A3), "r"(B0), "r"(B1))

__device__ __forceinline__ void cp16(uint32_t dst, const void* src) {
    asm volatile("cp.async.cg.shared.global [%0], [%1], 16;" :: "r"(dst), "l"(src));
}

// ---------------- all weight transposes in one kernel ------------------------
__global__ void transpose_all(const float* __restrict__ wq,
                              const float* __restrict__ wkv,
                              const float* __restrict__ wout,
                              float* __restrict__ wqt,
                              float* __restrict__ wkvt,
                              float* __restrict__ woutt, float scale) {
    int idx = blockIdx.x * 256 + threadIdx.x;
    if (idx < 16384) {
        int o = idx >> 7, c = idx & 127;
        wqt[c * 128 + o] = wq[idx] * scale;
    } else if (idx < 49152) {
        int i = idx - 16384;
        int o = i >> 7, c = i & 127;
        wkvt[c * 256 + o] = wkv[i];
    } else if (idx < 65536) {
        int i = idx - 49152;
        int o = i >> 7, c = i & 127;
        woutt[c * 128 + o] = wout[i];
    }
}

// ---------------- depthwise 3x3 compute, fp32 input --------------------------
__device__ __forceinline__ bool dw3_compute(const float* __restrict__ ip,
                                            int H, int W,
                                            const float* __restrict__ wc,
                                            float centerAdd, float binit,
                                            bool vec, int y0, int x0,
                                            float acc[4][4]) {
    float w0[3] = {wc[0], wc[3], wc[6]};
    float w1[3] = {wc[1], wc[4] + centerAdd, wc[7]};
    float w2[3] = {wc[2], wc[5], wc[8]};
#pragma unroll
    for (int r = 0; r < 4; r++)
#pragma unroll
        for (int j = 0; j < 4; j++) acc[r][j] = binit;

    bool fast = vec && (x0 >= 4) && (x0 + 8 <= W) && (y0 >= 1) && (y0 + 5 <= H);

    if (fast) {
#pragma unroll
        for (int iy = 0; iy < 6; iy++) {
            const float* rp = ip + (size_t)(y0 + iy - 1) * W;
            float4 mid = *(const float4*)(rp + x0);
            float v[6] = {rp[x0 - 1], mid.x, mid.y, mid.z, mid.w, rp[x0 + 4]};
#pragma unroll
            for (int r = 0; r < 4; r++) {
                int k = iy - r;
                if (k < 0 || k > 2) continue;
                float wy0 = w0[k], wy1 = w1[k], wy2 = w2[k];
#pragma unroll
                for (int j = 0; j < 4; j++)
                    acc[r][j] += v[j] * wy0 + v[j + 1] * wy1 + v[j + 2] * wy2;
            }
        }
    } else {
#pragma unroll
        for (int iy = 0; iy < 6; iy++) {
            int yy = y0 + iy - 1;
            if ((unsigned)yy >= (unsigned)H) continue;
            const float* rp = ip + (size_t)yy * W;
            float v[6];
#pragma unroll
            for (int i = 0; i < 6; i++) {
                int xx = x0 - 1 + i;
                v[i] = ((unsigned)xx < (unsigned)W) ? rp[xx] : 0.0f;
            }
#pragma unroll
            for (int r = 0; r < 4; r++) {
                int k = iy - r;
                if (k < 0 || k > 2) continue;
                float wy0 = w0[k], wy1 = w1[k], wy2 = w2[k];
#pragma unroll
                for (int j = 0; j < 4; j++)
                    acc[r][j] += v[j] * wy0 + v[j + 1] * wy1 + v[j + 2] * wy2;
            }
        }
    }
    return fast;
}

// ---------------- depthwise 3x3 compute, fp16 input --------------------------
__device__ __forceinline__ bool dw3_compute_h(const __half* __restrict__ ip,
                                              int H, int W,
                                              const float* __restrict__ wc,
                                              bool vec, int y0, int x0,
                                              float acc[4][4]) {
    float w0[3] = {wc[0], wc[3], wc[6]};
    float w1[3] = {wc[1], wc[4], wc[7]};
    float w2[3] = {wc[2], wc[5], wc[8]};
#pragma unroll
    for (int r = 0; r < 4; r++)
#pragma unroll
        for (int j = 0; j < 4; j++) acc[r][j] = 0.0f;

    bool fast = vec && (x0 >= 4) && (x0 + 8 <= W) && (y0 >= 1) && (y0 + 5 <= H);

    if (fast) {
#pragma unroll
        for (int iy = 0; iy < 6; iy++) {
            const __half* rp = ip + (size_t)(y0 + iy - 1) * W;
            uint2 m = *(const uint2*)(rp + x0);
            __half2 m01 = *reinterpret_cast<__half2*>(&m.x);
            __half2 m23 = *reinterpret_cast<__half2*>(&m.y);
            float2 f01 = __half22float2(m01);
            float2 f23 = __half22float2(m23);
            float v[6] = {__half2float(rp[x0 - 1]), f01.x, f01.y,
                          f23.x, f23.y, __half2float(rp[x0 + 4])};
#pragma unroll
            for (int r = 0; r < 4; r++) {
                int k = iy - r;
                if (k < 0 || k > 2) continue;
                float wy0 = w0[k], wy1 = w1[k], wy2 = w2[k];
#pragma unroll
                for (int j = 0; j < 4; j++)
                    acc[r][j] += v[j] * wy0 + v[j + 1] * wy1 + v[j + 2] * wy2;
            }
        }
    } else {
#pragma unroll
        for (int iy = 0; iy < 6; iy++) {
            int yy = y0 + iy - 1;
            if ((unsigned)yy >= (unsigned)H) continue;
            const __half* rp = ip + (size_t)yy * W;
            float v[6];
#pragma unroll
            for (int i = 0; i < 6; i++) {
                int xx = x0 - 1 + i;
                v[i] = ((unsigned)xx < (unsigned)W) ? __half2float(rp[xx]) : 0.0f;
            }
#pragma unroll
            for (int r = 0; r < 4; r++) {
                int k = iy - r;
                if (k < 0 || k > 2) continue;
                float wy0 = w0[k], wy1 = w1[k], wy2 = w2[k];
#pragma unroll
                for (int j = 0; j < 4; j++)
                    acc[r][j] += v[j] * wy0 + v[j + 1] * wy1 + v[j + 2] * wy2;
            }
        }
    }
    return fast;
}

// ---------------- pos dw3 uber (fp16 out) ------------------------------------
__global__ void dw3_pos_uber(const float* __restrict__ x, __half* __restrict__ xp,
                             const float* __restrict__ sp, __half* __restrict__ spp,
                             const float* __restrict__ w, const float* __restrict__ bias) {
    int py = blockIdx.y;
    const float* in; __half* out; int H, W; bool vec;
    int plane;
    if (py < BATCH * DIM) { plane = py; in = x; out = xp; H = W = HX; vec = true; }
    else { plane = py - BATCH * DIM; in = sp; out = spp; H = W = HS; vec = false; }
    int nqx = (W + 3) >> 2, nqy = (H + 3) >> 2;
    int qidx = blockIdx.x * 256 + threadIdx.x;
    if (qidx >= nqx * nqy) return;
    int y0 = (qidx / nqx) << 2, x0 = (qidx % nqx) << 2;
    int c = plane % DIM;
    int HW = H * W;
    float acc[4][4];
    bool fast = dw3_compute(in + (size_t)plane * HW, H, W, w + c * 9,
                            1.0f, bias[c], vec, y0, x0, acc);
    __half* opb = out + (size_t)plane * HW;
    if (fast) {
#pragma unroll
        for (int r = 0; r < 4; r++) {
            uint2 u = {h2pack(acc[r][0], acc[r][1]), h2pack(acc[r][2], acc[r][3])};
            *(uint2*)(opb + (size_t)(y0 + r) * W + x0) = u;
        }
    } else {
#pragma unroll
        for (int r = 0; r < 4; r++) {
            int yo = y0 + r;
            if (yo >= H) break;
#pragma unroll
            for (int j = 0; j < 4; j++) {
                int xo = x0 + j;
                if (xo < W) opb[(size_t)yo * W + xo] = __float2half_rn(acc[r][j]);
            }
        }
    }
}

// ---------------- qkv dw3 uber: fp16 in, fp16 mma-layout out -----------------
__global__ void dw3_qkv_uber(const float* __restrict__ wkvdw,
                             const float* __restrict__ wqdw) {
    int py = blockIdx.y;
    int qidx = blockIdx.x * 256 + threadIdx.x;

    if (py < BATCH * 64) {                       // ---- K pairs ----
        if (qidx >= 62 * 62) return;
        int b = py >> 6, cp = py & 63;
        int y0 = (qidx / 62) << 2, x0 = (qidx % 62) << 2;
        const __half* in0 = g_tkv + ((size_t)(b * 256 + 2 * cp)) * PS_X;
        float a0[4][4], a1[4][4];
        bool fast = dw3_compute_h(in0, HX, HX, wkvdw + (2 * cp) * 9, true, y0, x0, a0);
        dw3_compute_h(in0 + PS_X, HX, HX, wkvdw + (2 * cp + 1) * 9, true, y0, x0, a1);
        uint32_t* op = g_ki + ((size_t)(b * 64 + cp)) * PS_X;
        if (fast) {
#pragma unroll
            for (int r = 0; r < 4; r++) {
                uint4 u = {h2pack(a0[r][0], a1[r][0]), h2pack(a0[r][1], a1[r][1]),
                           h2pack(a0[r][2], a1[r][2]), h2pack(a0[r][3], a1[r][3])};
                *(uint4*)(op + (size_t)(y0 + r) * HX + x0) = u;
            }
        } else {
#pragma unroll
            for (int r = 0; r < 4; r++) {
                int yo = y0 + r;
                if (yo >= HX) break;
#pragma unroll
                for (int j = 0; j < 4; j++) {
                    int xo = x0 + j;
                    if (xo < HX)
                        op[(size_t)yo * HX + xo] = h2pack(a0[r][j], a1[r][j]);
                }
            }
        }
    } else if (py < BATCH * 64 + BATCH * 128) {  // ---- V plain ----
        if (qidx >= 62 * 62) return;
        int p = py - BATCH * 64;
        int b = p >> 7, c = p & 127;
        int y0 = (qidx / 62) << 2, x0 = (qidx % 62) << 2;
        const __half* in = g_tkv + ((size_t)(b * 256 + 128 + c)) * PS_X;
        float a[4][4];
        bool fast = dw3_compute_h(in, HX, HX, wkvdw + (128 + c) * 9, true, y0, x0, a);
        __half* op = g_v + ((size_t)(b * 128 + c)) * PS_X;
        if (fast) {
#pragma unroll
            for (int r = 0; r < 4; r++) {
                uint2 u = {h2pack(a[r][0], a[r][1]), h2pack(a[r][2], a[r][3])};
                *(uint2*)(op + (size_t)(y0 + r) * HX + x0) = u;
            }
        } else {
#pragma unroll
            for (int r = 0; r < 4; r++) {
                int yo = y0 + r;
                if (yo >= HX) break;
#pragma unroll
                for (int j = 0; j < 4; j++) {
                    int xo = x0 + j;
                    if (xo < HX) op[(size_t)yo * HX + xo] = __float2half_rn(a[r][j]);
                }
            }
        }
    } else {                                     // ---- Q pairs ----
        if (qidx >= 16 * 16) return;
        int p = py - BATCH * 64 - BATCH * 128;
        int b = p >> 6, cp = p & 63;
        int y0 = (qidx / 16) << 2, x0 = (qidx % 16) << 2;
        const __half* in0 = g_tq + ((size_t)(b * 128 + 2 * cp)) * PS_S;
        float a0[4][4], a1[4][4];
        dw3_compute_h(in0, HS, HS, wqdw + (2 * cp) * 9, false, y0, x0, a0);
        dw3_compute_h(in0 + PS_S, HS, HS, wqdw + (2 * cp + 1) * 9, false, y0, x0, a1);
        uint32_t* op = g_qi + ((size_t)(b * 64 + cp)) * PS_S;
#pragma unroll
        for (int r = 0; r < 4; r++) {
            int yo = y0 + r;
            if (yo >= HS) break;
#pragma unroll
            for (int j = 0; j < 4; j++) {
                int xo = x0 + j;
                if (xo < HS) op[(size_t)yo * HS + xo] = h2pack(a0[r][j], a1[r][j]);
            }
        }
    }
}

// ---------------- conv1 GEMM body (tf32 mma), templated I/O types ------------
template<typename TI, typename TO>
__device__ __forceinline__ void gemm128_body(
    const float* __restrict__ Wt, const TI* __restrict__ inb,
    TO* __restrict__ outb, int O, int P, int p0, int o0,
    uint32_t (*Ws)[16][136], uint32_t (*Xs)[16][136]) {

    constexpr bool IH = sizeof(TI) == 2;
    constexpr bool OH = sizeof(TO) == 2;

    int tid = threadIdx.x;
    int lane = tid & 31, warp = tid >> 5;
    int wo = warp >> 2;
    int wp = warp & 3;
    int g = lane >> 2;
    int tq = lane & 3;

    float c[4][4][4];
#pragma unroll
    for (int mi = 0; mi < 4; mi++)
#pragma unroll
        for (int ni = 0; ni < 4; ni++)
#pragma unroll
            for (int r = 0; r < 4; r++) c[mi][ni][r] = 0.0f;

    float wr[8], xr[8];

    auto fetch = [&](int kbase) {
#pragma unroll
        for (int l = 0; l < 8; l++) {
            int e = tid + l * 256;
            int k = e >> 7, o = e & 127;
            wr[l] = Wt[(size_t)(kbase + k) * O + o0 + o];
        }
        if (IH) {
#pragma unroll
            for (int l = 0; l < 4; l++) {
                int e2 = tid + l * 256;
                int k = e2 >> 6, o2 = (e2 & 63) * 2;
                int gp = p0 + o2;
                if (gp < P) {
                    __half2 hv = *(const __half2*)((const __half*)inb +
                                                   (size_t)(kbase + k) * P + gp);
                    float2 f = __half22float2(hv);
                    xr[2 * l] = f.x; xr[2 * l + 1] = f.y;
                } else { xr[2 * l] = 0.0f; xr[2 * l + 1] = 0.0f; }
            }
        } else {
#pragma unroll
            for (int l = 0; l < 8; l++) {
                int e = tid + l * 256;
                int k = e >> 7, o = e & 127;
                int gp = p0 + o;
                xr[l] = (gp < P) ? ((const float*)inb)[(size_t)(kbase + k) * P + gp] : 0.0f;
            }
        }
    };
    auto stash = [&](int buf) {
#pragma unroll
        for (int l = 0; l < 8; l++) {
            int e = tid + l * 256;
            int k = e >> 7, o = e & 127;
            Ws[buf][k][o] = f2tf32(wr[l]);
        }
        if (IH) {
#pragma unroll
            for (int l = 0; l < 4; l++) {
                int e2 = tid + l * 256;
                int k = e2 >> 6, o2 = (e2 & 63) * 2;
                Xs[buf][k][o2]     = f2tf32(xr[2 * l]);
                Xs[buf][k][o2 + 1] = f2tf32(xr[2 * l + 1]);
            }
        } else {
#pragma unroll
            for (int l = 0; l < 8; l++) {
                int e = tid + l * 256;
                int k = e >> 7, o = e & 127;
                Xs[buf][k][o] = f2tf32(xr[l]);
            }
        }
    };

    fetch(0);
    stash(0);
    __syncthreads();

    for (int kc = 0; kc < 8; kc++) {
        int cur = kc & 1;
        if (kc < 7) fetch((kc + 1) * 16);
#pragma unroll
        for (int s = 0; s < 2; s++) {
            int kb = s * 8;
            uint32_t bf[4][2];
#pragma unroll
            for (int ni = 0; ni < 4; ni++) {
                int col = wp * 32 + ni * 8 + g;
                bf[ni][0] = Xs[cur][kb + tq][col];
                bf[ni][1] = Xs[cur][kb + tq + 4][col];
            }
            uint32_t af[4][4];
#pragma unroll
            for (int mi = 0; mi < 4; mi++) {
                int row = wo * 64 + mi * 16 + g;
                af[mi][0] = Ws[cur][kb + tq][row];
                af[mi][1] = Ws[cur][kb + tq][row + 8];
                af[mi][2] = Ws[cur][kb + tq + 4][row];
                af[mi][3] = Ws[cur][kb + tq + 4][row + 8];
            }
#pragma unroll
            for (int mi = 0; mi < 4; mi++)
#pragma unroll
                for (int ni = 0; ni < 4; ni++)
                    MMA_TF32(c[mi][ni][0], c[mi][ni][1], c[mi][ni][2], c[mi][ni][3],
                             af[mi][0], af[mi][1], af[mi][2], af[mi][3],
                             bf[ni][0], bf[ni][1]);
        }
        if (kc < 7) stash(cur ^ 1);
        __syncthreads();
    }

#pragma unroll
    for (int mi = 0; mi < 4; mi++) {
        int row0 = o0 + wo * 64 + mi * 16 + g;
#pragma unroll
        for (int ni = 0; ni < 4; ni++) {
            int col = p0 + wp * 32 + ni * 8 + 2 * tq;
            if (col + 1 < P) {       // P even, col even => covers all valid cols
                if (OH) {
                    __half* o0p = (__half*)outb + (size_t)row0 * P + col;
                    __half* o1p = (__half*)outb + (size_t)(row0 + 8) * P + col;
                    *(__half2*)o0p = __floats2half2_rn(c[mi][ni][0], c[mi][ni][1]);
                    *(__half2*)o1p = __floats2half2_rn(c[mi][ni][2], c[mi][ni][3]);
                } else {
                    float* r0 = (float*)outb + (size_t)row0 * P + col;
                    float* r1 = (float*)outb + (size_t)(row0 + 8) * P + col;
                    r0[0] = c[mi][ni][0]; r0[1] = c[mi][ni][1];
                    r1[0] = c[mi][ni][2]; r1[1] = c[mi][ni][3];
                }
            }
        }
    }
}

#define NBLK_KV (481*2*BATCH)   // 1924
#define NBLK_Q  (31*BATCH)      // 62
__global__ __launch_bounds__(256, 2)
void conv1_uber(const float* __restrict__ wkvt, const __half* __restrict__ xp,
                __half* __restrict__ tkv,
                const float* __restrict__ wqt, const __half* __restrict__ spp,
                __half* __restrict__ tq) {
    __shared__ uint32_t Ws[2][16][136];
    __shared__ uint32_t Xs[2][16][136];
    int bid = blockIdx.x;
    if (bid < NBLK_KV) {
        int p0 = (bid % 481) * 128;
        int rest = bid / 481;
        int o0 = (rest & 1) * 128;
        int bz = rest >> 1;
        gemm128_body(wkvt, xp + (size_t)bz * 128 * PS_X,
                     tkv + (size_t)bz * 256 * PS_X, 256, PS_X, p0, o0, Ws, Xs);
    } else {
        int sid = bid - NBLK_KV;
        int p0 = (sid % 31) * 128;
        int bz = sid / 31;
        gemm128_body(wqt, spp + (size_t)bz * 128 * PS_S,
                     tq + (size_t)bz * 128 * PS_S, 128, PS_S, p0, 0, Ws, Xs);
    }
}

__global__ __launch_bounds__(256, 2)
void conv1_single(const float* __restrict__ Wt, const float* __restrict__ in,
                  float* __restrict__ out, int O, int P) {
    __shared__ uint32_t Ws[2][16][136];
    __shared__ uint32_t Xs[2][16][136];
    gemm128_body(Wt, in + (size_t)blockIdx.z * 128 * P,
                 out + (size_t)blockIdx.z * O * P, O, P,
                 blockIdx.x * 128, blockIdx.y * 128, Ws, Xs);
}

// ---------------- windowed attention: fp16 mma, zero-shuffle PV --------------
__global__ __launch_bounds__(128)
void attn_mma_kernel() {
    __shared__ uint32_t qs[16][72];       // [chpair][qpos]
    __shared__ uint32_t ks[2][16][72];    // [buf][chpair][kvpos]
    __shared__ uint32_t vs[2][32][36];    // [buf][ch][pospair]

    int bn = blockIdx.x;
    int h  = blockIdx.y;
    int b = bn / NWIN, n = bn % NWIN;
    int wh = n / 10, ww = n % 10;
    int tid = threadIdx.x, lane = tid & 31, warp = tid >> 5;
    int g = lane >> 2, tq = lane & 3;

    int y0q = 6 * wh, x0q = 6 * ww;
    int y0k = 24 * wh, x0k = 24 * ww;

    const int KSB = 16 * 72;
    const int VSB = 32 * 36;

    const uint32_t* ksrc[2]; uint32_t kdst[2];
#pragma unroll
    for (int t = 0; t < 2; t++) {
        int u = tid + t * 128;
        int cp = u >> 4, rem = u & 15, row = rem >> 3, xq = rem & 7;
        ksrc[t] = g_ki + ((size_t)(b * 64 + h * 16 + cp)) * PS_X
                + (y0k + row) * HX + x0k + xq * 4;
        kdst[t] = (uint32_t)__cvta_generic_to_shared(&ks[0][cp][row * 32 + xq * 4]);
    }
    const uint32_t* vsrc[2]; uint32_t vdst[2];
    const uint32_t* gv32 = (const uint32_t*)g_v;
#pragma unroll
    for (int t = 0; t < 2; t++) {
        int u = tid + t * 128;
        int ch = u >> 3, rem = u & 7, row = rem >> 2, xq = rem & 3;
        vsrc[t] = gv32 + (((size_t)(b * 128 + h * 32 + ch)) * PS_X
                          + (y0k + row) * HX + x0k) / 2 + xq * 4;
        vdst[t] = (uint32_t)__cvta_generic_to_shared(&vs[0][ch][row * 16 + xq * 4]);
    }

#pragma unroll
    for (int t = 0; t < 2; t++) cp16(kdst[t], ksrc[t]);
#pragma unroll
    for (int t = 0; t < 2; t++) cp16(vdst[t], vsrc[t]);
    asm volatile("cp.async.commit_group;" ::: "memory");

    const uint32_t* qsrc = g_qi + ((size_t)(b * 64 + h * 16)) * PS_S;
    for (int e = tid; e < 512; e += 128) {
        int cp = e >> 5, ip = e & 31;
        int i = ip * 2;
        int dy = i >> 3, dx = i & 7;
        uint2 v = *(const uint2*)(qsrc + (size_t)cp * PS_S + (y0q + dy) * HS + x0q + dx);
        qs[cp][i] = v.x;
        qs[cp][i + 1] = v.y;
    }

    float oacc[4][4];
#pragma unroll
    for (int ni = 0; ni < 4; ni++)
#pragma unroll
        for (int r = 0; r < 4; r++) oacc[ni][r] = 0.0f;
    float mrow0 = -1e30f, mrow1 = -1e30f, lrow0 = 0.0f, lrow1 = 0.0f;

    int m0 = warp * 16;

    for (int i = 0; i < 16; i++) {
        int cur = i & 1;
        if (i < 15) {
            int nb = cur ^ 1;
            int koff = (i + 1) * 2 * HX;
            int voff = (i + 1) * HX;
#pragma unroll
            for (int t = 0; t < 2; t++) cp16(kdst[t] + nb * KSB * 4, ksrc[t] + koff);
#pragma unroll
            for (int t = 0; t < 2; t++) cp16(vdst[t] + nb * VSB * 4, vsrc[t] + voff);
            asm volatile("cp.async.commit_group;" ::: "memory");
            asm volatile("cp.async.wait_group 1;" ::: "memory");
        } else {
            asm volatile("cp.async.wait_group 0;" ::: "memory");
        }
        __syncthreads();

        // ---- S = Q K^T (16 x 64 per warp), fp16 mma, log2 domain ----
        float sc[8][4];
#pragma unroll
        for (int ni = 0; ni < 8; ni++)
#pragma unroll
            for (int r = 0; r < 4; r++) sc[ni][r] = 0.0f;

#pragma unroll
        for (int k0 = 0; k0 < 2; k0++) {
            uint32_t a0 = qs[k0 * 8 + tq][m0 + g];
            uint32_t a1 = qs[k0 * 8 + tq][m0 + g + 8];
            uint32_t a2 = qs[k0 * 8 + tq + 4][m0 + g];
            uint32_t a3 = qs[k0 * 8 + tq + 4][m0 + g + 8];
#pragma unroll
            for (int ni = 0; ni < 8; ni++) {
                uint32_t b0 = ks[cur][k0 * 8 + tq][ni * 8 + g];
                uint32_t b1 = ks[cur][k0 * 8 + tq + 4][ni * 8 + g];
                MMA_F16(sc[ni][0], sc[ni][1], sc[ni][2], sc[ni][3],
                        a0, a1, a2, a3, b0, b1);
            }
        }

        // ---- streaming softmax (base-2) ----
        float mx0 = -1e30f, mx1 = -1e30f;
#pragma unroll
        for (int ni = 0; ni < 8; ni++) {
            mx0 = fmaxf(mx0, fmaxf(sc[ni][0], sc[ni][1]));
            mx1 = fmaxf(mx1, fmaxf(sc[ni][2], sc[ni][3]));
        }
#pragma unroll
        for (int off = 1; off <= 2; off <<= 1) {
            mx0 = fmaxf(mx0, __shfl_xor_sync(0xFFFFFFFFu, mx0, off));
            mx1 = fmaxf(mx1, __shfl_xor_sync(0xFFFFFFFFu, mx1, off));
        }
        float mn0 = fmaxf(mrow0, mx0), mn1 = fmaxf(mrow1, mx1);
        float cor0 = ex2(mrow0 - mn0), cor1 = ex2(mrow1 - mn1);
        mrow0 = mn0; mrow1 = mn1;

        float s0 = 0.0f, s1 = 0.0f;
#pragma unroll
        for (int ni = 0; ni < 8; ni++) {
            sc[ni][0] = ex2(sc[ni][0] - mn0);
            sc[ni][1] = ex2(sc[ni][1] - mn0);
            sc[ni][2] = ex2(sc[ni][2] - mn1);
            sc[ni][3] = ex2(sc[ni][3] - mn1);
            s0 += sc[ni][0] + sc[ni][1];
            s1 += sc[ni][2] + sc[ni][3];
        }
#pragma unroll
        for (int off = 1; off <= 2; off <<= 1) {
            s0 += __shfl_xor_sync(0xFFFFFFFFu, s0, off);
            s1 += __shfl_xor_sync(0xFFFFFFFFu, s1, off);
        }
        lrow0 = lrow0 * cor0 + s0;
        lrow1 = lrow1 * cor1 + s1;
#pragma unroll
        for (int ni = 0; ni < 4; ni++) {
            oacc[ni][0] *= cor0; oacc[ni][1] *= cor0;
            oacc[ni][2] *= cor1; oacc[ni][3] *= cor1;
        }

        // ---- O += P V : A-frags are repacked C-frags (NO shuffles) ----
#pragma unroll
        for (int kk = 0; kk < 4; kk++) {
            uint32_t a0 = h2pack(sc[2 * kk][0],     sc[2 * kk][1]);
            uint32_t a1 = h2pack(sc[2 * kk][2],     sc[2 * kk][3]);
            uint32_t a2 = h2pack(sc[2 * kk + 1][0], sc[2 * kk + 1][1]);
            uint32_t a3 = h2pack(sc[2 * kk + 1][2], sc[2 * kk + 1][3]);
#pragma unroll
            for (int ni = 0; ni < 4; ni++) {
                uint32_t b0 = vs[cur][ni * 8 + g][kk * 8 + tq];
                uint32_t b1 = vs[cur][ni * 8 + g][kk * 8 + tq + 4];
                MMA_F16(oacc[ni][0], oacc[ni][1], oacc[ni][2], oacc[ni][3],
                        a0, a1, a2, a3, b0, b1);
            }
        }
        __syncthreads();
    }

    float inv0 = 1.0f / lrow0, inv1 = 1.0f / lrow1;
#pragma unroll
    for (int ni = 0; ni < 4; ni++) {
        int col = h * 32 + ni * 8 + 2 * tq;
        size_t base = (size_t)bn * DIM;
        g_win[(base + col) * 64 + m0 + g]         = oacc[ni][0] * inv0;
        g_win[(base + col + 1) * 64 + m0 + g]     = oacc[ni][1] * inv0;
        g_win[(base + col) * 64 + m0 + g + 8]     = oacc[ni][2] * inv1;
        g_win[(base + col + 1) * 64 + m0 + g + 8] = oacc[ni][3] * inv1;
    }
}

// ---------------- reverse (overlap-add with count normalization) -------------
__global__ void reverse_kernel() {
    int idx = blockIdx.x * 256 + threadIdx.x;
    int half = BATCH * DIM * PS_S / 2;
    if (idx >= half + (BATCH * DIM * PS_S & 1)) return;
    int base2 = idx * 2;
    int x = base2 % HS;
    int y = (base2 / HS) % HS;
    int c = (base2 / PS_S) % DIM;
    int b = base2 / (PS_S * DIM);

    float o[2];
#pragma unroll
    for (int t = 0; t < 2; t++) {
        int xx = x + t;
        float s = 0.0f;
        int cnt = 0;
        if (xx < HS) {
            int wlo = max(0, (y - 2) / 6), whi = min(9, y / 6);
            int vlo = max(0, (xx - 2) / 6), vhi = min(9, xx / 6);
            for (int wh = wlo; wh <= whi; wh++) {
                int dy = y - 6 * wh;
                for (int ww = vlo; ww <= vhi; ww++) {
                    int dx = xx - 6 * ww;
                    int n = wh * 10 + ww;
                    s += g_win[((size_t)(b * NWIN + n) * DIM + c) * 64 + dy * 8 + dx];
                }
            }
            cnt = (whi - wlo + 1) * (vhi - vlo + 1);
        }
        o[t] = cnt ? s / (float)cnt : 0.0f;
    }
    float* op = g_acc + (size_t)base2;
    op[0] = o[0];
    if (x + 1 < HS) op[1] = o[1];
}

// ---------------- launch -----------------------------------------------------
extern "C" void kernel_launch(void* const* d_in, const int* in_sizes, int n_in,
                              void* d_out, int out_size) {
    const float* x     = (const float*)d_in[0];
    const float* sp    = (const float*)d_in[1];
    const float* w_pos = (const float*)d_in[2];
    const float* b_pos = (const float*)d_in[3];
    const float* w_q   = (const float*)d_in[4];
    const float* w_qdw = (const float*)d_in[5];
    const float* w_kv  = (const float*)d_in[6];
    const float* w_kvdw= (const float*)d_in[7];
    const float* w_out = (const float*)d_in[8];
    float* out = (float*)d_out;

    __half *xp, *spp, *tkv, *tq;
    float *acc, *wq_t, *wkv_t, *wout_t;
    cudaGetSymbolAddress((void**)&xp,    g_xp);
    cudaGetSymbolAddress((void**)&spp,   g_spp);
    cudaGetSymbolAddress((void**)&tkv,   g_tkv);
    cudaGetSymbolAddress((void**)&tq,    g_tq);
    cudaGetSymbolAddress((void**)&acc,   g_acc);
    cudaGetSymbolAddress((void**)&wq_t,  g_wq_t);
    cudaGetSymbolAddress((void**)&wkv_t, g_wkv_t);
    cudaGetSymbolAddress((void**)&wout_t,g_wout_t);

    // 1/sqrt(32) * log2(e): attention S computed in log2 domain
    const float scale = 0.17677669529663687f * 1.44269504088896340736f;
    transpose_all<<<256, 256>>>(w_q, w_kv, w_out, wq_t, wkv_t, wout_t, scale);

    dw3_pos_uber<<<dim3(16, BATCH*DIM*2), 256>>>(x, xp, sp, spp, w_pos, b_pos);

    conv1_uber<<<NBLK_KV + NBLK_Q, 256>>>(wkv_t, xp, tkv, wq_t, spp, tq);

    dw3_qkv_uber<<<dim3(16, BATCH*64 + BATCH*128 + BATCH*64), 256>>>(w_kvdw, w_qdw);

    attn_mma_kernel<<<dim3(BATCH*NWIN, 4), 128>>>();

    reverse_kernel<<<(BATCH*DIM*PS_S/2 + 255)/256, 256>>>();

    conv1_single<<<dim3((PS_S + 127)/128, 1, BATCH), 256>>>(wout_t, acc, out, DIM, PS_S);
}